// round 8
// baseline (speedup 1.0000x reference)
#include <cuda_runtime.h>
#include <cuda_fp16.h>
#include <cstdint>

#define NTOK 8192
#define DIN  512
#define DHEAD 256
#define NSPLIT 2
#define BM 128
#define BN 64
#define JBLOCKS (NTOK / NSPLIT / BN)   // 64

// ---------------- scratch ----------------
__device__ __half  g_Fhi[NTOK * DIN];         // feat hi fp16
__device__ __half  g_Flo[NTOK * DIN];         // feat residual fp16
__device__ __half2 g_Wp[3 * (DIN / 2) * DHEAD];  // W packed (k-pairs)
__device__ __half  g_Qh[NTOK * DHEAD];        // fp16, pre-scaled by 1/16
__device__ __half  g_Kh[NTOK * DHEAD];        // fp16
__device__ __half  g_Vt[DHEAD * NTOK];        // V transposed [d][tok], fp16
__device__ float   g_Op[NSPLIT][NTOK][DHEAD];
__device__ float   g_ls[NSPLIT][NTOK];

// ---------------- helpers ----------------
__device__ __forceinline__ uint32_t smem_u32(const void* p) {
    uint32_t a;
    asm("{ .reg .u64 t; cvta.to.shared.u64 t, %1; cvt.u32.u64 %0, t; }" : "=r"(a) : "l"(p));
    return a;
}
__device__ __forceinline__ void cp16(uint32_t dst, const void* src) {
    asm volatile("cp.async.cg.shared.global [%0], [%1], 16;" :: "r"(dst), "l"(src));
}
__device__ __forceinline__ void cp8(uint32_t dst, const void* src) {
    asm volatile("cp.async.ca.shared.global [%0], [%1], 8;" :: "r"(dst), "l"(src));
}
#define CP_COMMIT() asm volatile("cp.async.commit_group;" ::: "memory")
#define CP_WAIT(n)  asm volatile("cp.async.wait_group %0;" :: "n"(n) : "memory")

__device__ __forceinline__ void ldsm4(unsigned& r0, unsigned& r1, unsigned& r2, unsigned& r3,
                                      uint32_t a) {
    asm volatile("ldmatrix.sync.aligned.m8n8.x4.shared.b16 {%0,%1,%2,%3}, [%4];"
                 : "=r"(r0), "=r"(r1), "=r"(r2), "=r"(r3) : "r"(a));
}

__device__ __forceinline__ void mma_f16(float& c0, float& c1, float& c2, float& c3,
                                        unsigned a0, unsigned a1, unsigned a2, unsigned a3,
                                        unsigned b0, unsigned b1) {
    asm volatile(
        "mma.sync.aligned.m16n8k16.row.col.f32.f16.f16.f32 "
        "{%0,%1,%2,%3}, {%4,%5,%6,%7}, {%8,%9}, {%0,%1,%2,%3};"
        : "+f"(c0), "+f"(c1), "+f"(c2), "+f"(c3)
        : "r"(a0), "r"(a1), "r"(a2), "r"(a3), "r"(b0), "r"(b1));
}

// ---------------- kernel 0: pre-split feat and pack W ----------------
__global__ __launch_bounds__(256) void prep_kernel(const float* __restrict__ feat,
                                                   const float* __restrict__ Wq,
                                                   const float* __restrict__ Wk,
                                                   const float* __restrict__ Wv) {
    const int idx = blockIdx.x * 256 + threadIdx.x;
    const int NF4 = NTOK * DIN / 4;
    if (idx < NF4) {
        float4 v = ((const float4*)feat)[idx];
        __half hx = __float2half_rn(v.x), hy = __float2half_rn(v.y);
        __half hz = __float2half_rn(v.z), hw = __float2half_rn(v.w);
        __half2 hi0 = __halves2half2(hx, hy), hi1 = __halves2half2(hz, hw);
        __half2 lo0 = __halves2half2(__float2half_rn(v.x - __half2float(hx)),
                                     __float2half_rn(v.y - __half2float(hy)));
        __half2 lo1 = __halves2half2(__float2half_rn(v.z - __half2float(hz)),
                                     __float2half_rn(v.w - __half2float(hw)));
        uint2 uh, ul;
        uh.x = *(unsigned*)&hi0; uh.y = *(unsigned*)&hi1;
        ul.x = *(unsigned*)&lo0; ul.y = *(unsigned*)&lo1;
        ((uint2*)g_Fhi)[idx] = uh;
        ((uint2*)g_Flo)[idx] = ul;
    } else {
        int j = idx - NF4;
        const int WSZ = (DIN / 2) * DHEAD;
        if (j < 3 * WSZ) {
            int mat = j / WSZ;
            int r = j - mat * WSZ;
            int k2 = r / DHEAD, n = r % DHEAD;
            const float* __restrict__ W = (mat == 0) ? Wq : ((mat == 1) ? Wk : Wv);
            g_Wp[j] = __halves2half2(__float2half_rn(W[(size_t)(2 * k2) * DHEAD + n]),
                                     __float2half_rn(W[(size_t)(2 * k2 + 1) * DHEAD + n]));
        }
    }
}

// ---------------- kernel 1: QKV projection, fp16 x2, conversion-free mainloop ----------------
__global__ __launch_bounds__(256) void proj_kernel() {
    __shared__ __half2 As[2][128][8];   // [hi/lo][row][k2 ^ (row&7)]
    __shared__ __half2 Bs[128][8];      // [col][k2 ^ (col&7)]

    const int tid = threadIdx.x;
    const int w = tid >> 5, lane = tid & 31, g = lane >> 2, t = lane & 3;
    const int wm = w >> 1, wn = w & 1;
    const int m0 = blockIdx.x * 128;
    const int n0 = blockIdx.y * 128;
    const int mat = blockIdx.z;
    const __half2* __restrict__ Wp = &g_Wp[mat * (DIN / 2) * DHEAD];

    float acc[2][8][4];
#pragma unroll
    for (int mt = 0; mt < 2; mt++)
#pragma unroll
        for (int nt = 0; nt < 8; nt++)
#pragma unroll
            for (int j = 0; j < 4; j++) acc[mt][nt][j] = 0.f;

    for (int kb = 0; kb < DIN; kb += 16) {
#pragma unroll
        for (int i = 0; i < 2; i++) {
            int e = tid + 256 * i;
            int r = e >> 2, c = (e & 3) << 2;
            size_t off = (size_t)(m0 + r) * DIN + kb + c;
            uint2 uh = *(const uint2*)&g_Fhi[off];
            uint2 ul = *(const uint2*)&g_Flo[off];
            int p0 = c >> 1, rm = r & 7;
            *(unsigned*)&As[0][r][p0 ^ rm] = uh.x;
            *(unsigned*)&As[0][r][(p0 + 1) ^ rm] = uh.y;
            *(unsigned*)&As[1][r][p0 ^ rm] = ul.x;
            *(unsigned*)&As[1][r][(p0 + 1) ^ rm] = ul.y;
        }
#pragma unroll
        for (int i = 0; i < 4; i++) {
            int idx = tid + 256 * i;
            int n = idx & 127, k2l = idx >> 7;
            Bs[n][k2l ^ (n & 7)] = Wp[(size_t)(kb / 2 + k2l) * DHEAD + n0 + n];
        }
        __syncthreads();

        unsigned b[8][2];
#pragma unroll
        for (int nt = 0; nt < 8; nt++) {
            int n = 64 * wn + 8 * nt + g, nm = n & 7;
            b[nt][0] = *(const unsigned*)&Bs[n][t ^ nm];
            b[nt][1] = *(const unsigned*)&Bs[n][(t + 4) ^ nm];
        }
#pragma unroll
        for (int sp = 0; sp < 2; sp++) {
#pragma unroll
            for (int mt = 0; mt < 2; mt++) {
                int r = 32 * wm + 16 * mt + g, rm = r & 7;
                unsigned a0 = *(const unsigned*)&As[sp][r][t ^ rm];
                unsigned a1 = *(const unsigned*)&As[sp][r + 8][t ^ rm];
                unsigned a2 = *(const unsigned*)&As[sp][r][(t + 4) ^ rm];
                unsigned a3 = *(const unsigned*)&As[sp][r + 8][(t + 4) ^ rm];
#pragma unroll
                for (int nt = 0; nt < 8; nt++)
                    mma_f16(acc[mt][nt][0], acc[mt][nt][1], acc[mt][nt][2], acc[mt][nt][3],
                            a0, a1, a2, a3, b[nt][0], b[nt][1]);
            }
        }
        __syncthreads();
    }

    const float scale = (mat == 0) ? 0.0625f : 1.0f;
#pragma unroll
    for (int mt = 0; mt < 2; mt++) {
        int r = m0 + 32 * wm + 16 * mt + g;
#pragma unroll
        for (int nt = 0; nt < 8; nt++) {
            int col = n0 + 64 * wn + 8 * nt + 2 * t;
            __half h00 = __float2half_rn(acc[mt][nt][0] * scale);
            __half h01 = __float2half_rn(acc[mt][nt][1] * scale);
            __half h10 = __float2half_rn(acc[mt][nt][2] * scale);
            __half h11 = __float2half_rn(acc[mt][nt][3] * scale);
            if (mat == 2) {
                g_Vt[(size_t)col * NTOK + r] = h00;
                g_Vt[(size_t)(col + 1) * NTOK + r] = h01;
                g_Vt[(size_t)col * NTOK + r + 8] = h10;
                g_Vt[(size_t)(col + 1) * NTOK + r + 8] = h11;
            } else {
                __half* dst = (mat == 0) ? g_Qh : g_Kh;
                *(__half2*)&dst[(size_t)r * DHEAD + col] = __halves2half2(h00, h01);
                *(__half2*)&dst[(size_t)(r + 8) * DHEAD + col] = __halves2half2(h10, h11);
            }
        }
    }
}

// ---------------- kernel 2: pipelined fp16 attention, 3 barriers/iter ----------------
// SMEM layout (bytes):
#define SMO_Q   0u        // [128][256] half, row stride 512B, 16B-granule xor swizzle
#define SMO_K0  65536u    // [64][256] half
#define SMO_K1  98304u
#define SMO_V   131072u   // [256][64] half (V^T), row stride 128B
#define SMO_CP  163840u   // per-thread cnt slots: 256 x 136B
#define SMO_P   198656u   // [128] rows x 144B, linear
#define SMO_L   217088u   // 256 floats
#define SMEM_DYN (217088u + 1024u)

__global__ __launch_bounds__(256, 1) void attn_kernel(const float* __restrict__ cnt) {
    extern __shared__ char sm[];
    const uint32_t sb = smem_u32(sm);

    const int tid = threadIdx.x, w = tid >> 5, lane = tid & 31;
    const int g = lane >> 2, t = lane & 3;
    const int wm = w & 3, wh = w >> 2;     // 4 m-warps x 2 n/d-half warps
    const int m0 = blockIdx.x * BM;
    const int sp = blockIdx.y;
    const int jb0 = sp * (NTOK / NSPLIT);

    // ldmatrix lane decomposition
    const int lr = lane & 7;
    const int lm = (lane >> 3) & 1;
    const int lh = lane >> 4;

    const int ar0 = 32 * wm + lr + 8 * lm;
    const uint32_t qb0 = sb + SMO_Q + (uint32_t)ar0 * 512u;
    const uint32_t qb1 = qb0 + 16u * 512u;
    const uint32_t pb0 = sb + SMO_P + (uint32_t)ar0 * 144u;
    const uint32_t pb1 = pb0 + 16u * 144u;
    const int bnr = lr + 8 * lh;
    const uint32_t kroff = (uint32_t)(32 * wh + bnr) * 512u;
    const uint32_t vb = sb + SMO_V + (uint32_t)(128 * wh + bnr) * 128u;

    const int rA0 = 32 * wm + g, rB0 = rA0 + 8;

    // per-thread cnt slot base + the 4 global row bases this thread reads
    const uint32_t cslot = sb + SMO_CP + (uint32_t)tid * 136u;
    const float* crow[4];
#pragma unroll
    for (int mt = 0; mt < 2; mt++) {
        crow[2 * mt + 0] = &cnt[(size_t)(m0 + rA0 + 16 * mt) * NTOK + 32 * wh + 2 * t];
        crow[2 * mt + 1] = &cnt[(size_t)(m0 + rB0 + 16 * mt) * NTOK + 32 * wh + 2 * t];
    }

    // ---- prologue: Q tile + K_0 via cp.async (group 0) ----
#pragma unroll
    for (int i = 0; i < 16; i++) {
        int e = tid + 256 * i;
        int r = e >> 5, blk = e & 31;
        uint32_t d = sb + SMO_Q + (uint32_t)r * 512u + (uint32_t)((blk ^ (r & 7)) << 4);
        cp16(d, &g_Qh[(size_t)(m0 + r) * DHEAD + 8 * blk]);
    }
#pragma unroll
    for (int i = 0; i < 8; i++) {
        int e = tid + 256 * i;
        int r = e >> 5, blk = e & 31;
        uint32_t d = sb + SMO_K0 + (uint32_t)r * 512u + (uint32_t)((blk ^ (r & 7)) << 4);
        cp16(d, &g_Kh[(size_t)(jb0 + r) * DHEAD + 8 * blk]);
    }
    CP_COMMIT();

    float O[2][16][4];
#pragma unroll
    for (int mt = 0; mt < 2; mt++)
#pragma unroll
        for (int nt = 0; nt < 16; nt++)
#pragma unroll
            for (int q = 0; q < 4; q++) O[mt][nt][q] = 0.f;
    float lA[2] = {0.f, 0.f}, lB[2] = {0.f, 0.f};

    for (int j = 0; j < JBLOCKS; j++) {
        const int jb = jb0 + j * BN;
        __syncthreads();   // barrier 1: prev AV done with V/P; K[(j+1)&1] free

        // ---- issue V_j + private cnt slice (one group) ----
#pragma unroll
        for (int i = 0; i < 8; i++) {
            int e = tid + 256 * i;
            int dd = e >> 3, blk = e & 7;
            uint32_t d = sb + SMO_V + (uint32_t)dd * 128u + (uint32_t)((blk ^ (dd & 7)) << 4);
            cp16(d, &g_Vt[(size_t)dd * NTOK + jb + 8 * blk]);
        }
#pragma unroll
        for (int q = 0; q < 4; q++)
#pragma unroll
            for (int nt = 0; nt < 4; nt++)
                cp8(cslot + (uint32_t)(q * 4 + nt) * 8u, crow[q] + jb + 8 * nt);
        CP_COMMIT();

        // ---- issue K_{j+1} ----
        if (j + 1 < JBLOCKS) {
            uint32_t kb = ((j + 1) & 1) ? SMO_K1 : SMO_K0;
#pragma unroll
            for (int i = 0; i < 8; i++) {
                int e = tid + 256 * i;
                int r = e >> 5, blk = e & 31;
                uint32_t d = sb + kb + (uint32_t)r * 512u + (uint32_t)((blk ^ (r & 7)) << 4);
                cp16(d, &g_Kh[(size_t)(jb + BN + r) * DHEAD + 8 * blk]);
            }
        }
        CP_COMMIT();

        CP_WAIT(2);        // K_j (and Q on j=0) complete
        __syncthreads();   // barrier 2: K visible

        // ---- QK_j ----
        const uint32_t kbuf = sb + ((j & 1) ? SMO_K1 : SMO_K0) + kroff;
        float S[2][4][4];
#pragma unroll
        for (int mt = 0; mt < 2; mt++)
#pragma unroll
            for (int nt = 0; nt < 4; nt++)
#pragma unroll
                for (int q = 0; q < 4; q++) S[mt][nt][q] = 0.f;

#pragma unroll
        for (int s = 0; s < 16; s++) {
            const uint32_t xa = (uint32_t)(((2 * s + lh) ^ lr) << 4);
            const uint32_t xb = (uint32_t)(((2 * s + lm) ^ lr) << 4);
            unsigned a0[4], a1[4], b0[4], b1[4];
            ldsm4(a0[0], a0[1], a0[2], a0[3], qb0 + xa);
            ldsm4(a1[0], a1[1], a1[2], a1[3], qb1 + xa);
            ldsm4(b0[0], b0[1], b0[2], b0[3], kbuf + xb);
            ldsm4(b1[0], b1[1], b1[2], b1[3], kbuf + 16u * 512u + xb);
            mma_f16(S[0][0][0], S[0][0][1], S[0][0][2], S[0][0][3], a0[0], a0[1], a0[2], a0[3], b0[0], b0[1]);
            mma_f16(S[0][1][0], S[0][1][1], S[0][1][2], S[0][1][3], a0[0], a0[1], a0[2], a0[3], b0[2], b0[3]);
            mma_f16(S[0][2][0], S[0][2][1], S[0][2][2], S[0][2][3], a0[0], a0[1], a0[2], a0[3], b1[0], b1[1]);
            mma_f16(S[0][3][0], S[0][3][1], S[0][3][2], S[0][3][3], a0[0], a0[1], a0[2], a0[3], b1[2], b1[3]);
            mma_f16(S[1][0][0], S[1][0][1], S[1][0][2], S[1][0][3], a1[0], a1[1], a1[2], a1[3], b0[0], b0[1]);
            mma_f16(S[1][1][0], S[1][1][1], S[1][1][2], S[1][1][3], a1[0], a1[1], a1[2], a1[3], b0[2], b0[3]);
            mma_f16(S[1][2][0], S[1][2][1], S[1][2][2], S[1][2][3], a1[0], a1[1], a1[2], a1[3], b1[0], b1[1]);
            mma_f16(S[1][3][0], S[1][3][1], S[1][3][2], S[1][3][3], a1[0], a1[1], a1[2], a1[3], b1[2], b1[3]);
        }

        CP_WAIT(1);        // own V+cnt group complete; private cnt readable NOW (no barrier)

        // ---- epilogue: P = exp(S) * cnt -> Ps (fp16), accumulate l ----
        char* Ps = sm + SMO_P;
#pragma unroll
        for (int mt = 0; mt < 2; mt++) {
            int rA = rA0 + 16 * mt, rB = rB0 + 16 * mt;
            float sA = 0.f, sB = 0.f;
#pragma unroll
            for (int nt = 0; nt < 4; nt++) {
                float2 cA = *(const float2*)(sm + (cslot - sb) + (uint32_t)((2 * mt) * 4 + nt) * 8u);
                float2 cB = *(const float2*)(sm + (cslot - sb) + (uint32_t)((2 * mt + 1) * 4 + nt) * 8u);
                float p0 = __expf(S[mt][nt][0]) * cA.x;
                float p1 = __expf(S[mt][nt][1]) * cA.y;
                float p2 = __expf(S[mt][nt][2]) * cB.x;
                float p3 = __expf(S[mt][nt][3]) * cB.y;
                sA += p0 + p1;
                sB += p2 + p3;
                int q = (16 * wh + 4 * nt + t) << 2;
                *(__half2*)(Ps + rA * 144 + q) = __halves2half2(__float2half_rn(p0), __float2half_rn(p1));
                *(__half2*)(Ps + rB * 144 + q) = __halves2half2(__float2half_rn(p2), __float2half_rn(p3));
            }
            sA += __shfl_xor_sync(0xffffffffu, sA, 1);
            sA += __shfl_xor_sync(0xffffffffu, sA, 2);
            sB += __shfl_xor_sync(0xffffffffu, sB, 1);
            sB += __shfl_xor_sync(0xffffffffu, sB, 2);
            lA[mt] += sA;
            lB[mt] += sB;
        }
        __syncthreads();   // barrier 3: P + V visible to all warps

        // ---- AV_j : O += P @ V^T ----
#pragma unroll
        for (int s = 0; s < 4; s++) {
            const uint32_t xp = (uint32_t)((2 * s + lh) << 4);
            const uint32_t xv = (uint32_t)(((2 * s + lm) ^ lr) << 4);
            unsigned pa0[4], pa1[4];
            ldsm4(pa0[0], pa0[1], pa0[2], pa0[3], pb0 + xp);
            ldsm4(pa1[0], pa1[1], pa1[2], pa1[3], pb1 + xp);
#pragma unroll
            for (int p = 0; p < 8; p++) {
                unsigned vv[4];
                ldsm4(vv[0], vv[1], vv[2], vv[3], vb + (uint32_t)p * 2048u + xv);
                mma_f16(O[0][2 * p][0], O[0][2 * p][1], O[0][2 * p][2], O[0][2 * p][3],
                        pa0[0], pa0[1], pa0[2], pa0[3], vv[0], vv[1]);
                mma_f16(O[0][2 * p + 1][0], O[0][2 * p + 1][1], O[0][2 * p + 1][2], O[0][2 * p + 1][3],
                        pa0[0], pa0[1], pa0[2], pa0[3], vv[2], vv[3]);
                mma_f16(O[1][2 * p][0], O[1][2 * p][1], O[1][2 * p][2], O[1][2 * p][3],
                        pa1[0], pa1[1], pa1[2], pa1[3], vv[0], vv[1]);
                mma_f16(O[1][2 * p + 1][0], O[1][2 * p + 1][1], O[1][2 * p + 1][2], O[1][2 * p + 1][3],
                        pa1[0], pa1[1], pa1[2], pa1[3], vv[2], vv[3]);
            }
        }
    }

    // ---- O writeout ----
#pragma unroll
    for (int mt = 0; mt < 2; mt++) {
        int rA = m0 + rA0 + 16 * mt, rB = m0 + rB0 + 16 * mt;
#pragma unroll
        for (int nt = 0; nt < 16; nt++) {
            int col = 128 * wh + 8 * nt + 2 * t;
            *(float2*)&g_Op[sp][rA][col] = make_float2(O[mt][nt][0], O[mt][nt][1]);
            *(float2*)&g_Op[sp][rB][col] = make_float2(O[mt][nt][2], O[mt][nt][3]);
        }
    }

    // ---- l reduce across the two wh warps ----
    float* Lr = (float*)(sm + SMO_L);
    if (t == 0) {
#pragma unroll
        for (int mt = 0; mt < 2; mt++) {
            Lr[wh * 128 + rA0 + 16 * mt] = lA[mt];
            Lr[wh * 128 + rB0 + 16 * mt] = lB[mt];
        }
    }
    __syncthreads();
    if (tid < 128) g_ls[sp][m0 + tid] = Lr[tid] + Lr[128 + tid];
}

// ---------------- kernel 3: combine + ELU ----------------
__global__ __launch_bounds__(256) void combine_kernel(float* __restrict__ out) {
    const int i = blockIdx.x;
    const int d = threadIdx.x;
    float den = g_ls[0][i] + g_ls[1][i];
    float num = g_Op[0][i][d] + g_Op[1][i][d];
    float r = num / den;
    out[(size_t)i * DHEAD + d] = (r > 0.f) ? r : expm1f(r);
}

// ---------------- launch ----------------
extern "C" void kernel_launch(void* const* d_in, const int* in_sizes, int n_in,
                              void* d_out, int out_size) {
    (void)in_sizes; (void)n_in; (void)out_size;
    const float* feat = (const float*)d_in[0];
    const float* cnt = (const float*)d_in[1];
    const float* Wq = (const float*)d_in[2];
    const float* Wk = (const float*)d_in[3];
    const float* Wv = (const float*)d_in[4];

    const int NPREP = (NTOK * DIN / 4 + 3 * (DIN / 2) * DHEAD + 255) / 256;
    prep_kernel<<<NPREP, 256>>>(feat, Wq, Wk, Wv);

    proj_kernel<<<dim3(NTOK / 128, DHEAD / 128, 3), 256>>>();

    cudaFuncSetAttribute(attn_kernel, cudaFuncAttributeMaxDynamicSharedMemorySize, (int)SMEM_DYN);
    attn_kernel<<<dim3(NTOK / BM, NSPLIT), 256, SMEM_DYN>>>(cnt);

    combine_kernel<<<NTOK, 256>>>((float*)d_out);
}

// round 9
// speedup vs baseline: 1.1960x; 1.1960x over previous
#include <cuda_runtime.h>
#include <cuda_fp16.h>
#include <cstdint>

#define NTOK 8192
#define DIN  512
#define DHEAD 256
#define NSPLIT 2
#define BM 128
#define BN 64
#define JBLOCKS (NTOK / NSPLIT / BN)   // 64

// ---------------- scratch ----------------
__device__ __half2 g_Wp[3 * (DIN / 2) * DHEAD];  // W packed as k-pairs, fp16
__device__ __half  g_Qh[NTOK * DHEAD];        // fp16, pre-scaled by 1/16
__device__ __half  g_Kh[NTOK * DHEAD];        // fp16
__device__ __half  g_Vt[DHEAD * NTOK];        // V transposed [d][tok], fp16
__device__ float   g_Op[NSPLIT][NTOK][DHEAD];
__device__ float   g_ls[NSPLIT][NTOK];

// ---------------- helpers ----------------
__device__ __forceinline__ uint32_t smem_u32(const void* p) {
    uint32_t a;
    asm("{ .reg .u64 t; cvta.to.shared.u64 t, %1; cvt.u32.u64 %0, t; }" : "=r"(a) : "l"(p));
    return a;
}
__device__ __forceinline__ void cp16(uint32_t dst, const void* src) {
    asm volatile("cp.async.cg.shared.global [%0], [%1], 16;" :: "r"(dst), "l"(src));
}
#define CP_COMMIT() asm volatile("cp.async.commit_group;" ::: "memory")
#define CP_WAIT(n)  asm volatile("cp.async.wait_group %0;" :: "n"(n) : "memory")

__device__ __forceinline__ void ldsm4(unsigned& r0, unsigned& r1, unsigned& r2, unsigned& r3,
                                      uint32_t a) {
    asm volatile("ldmatrix.sync.aligned.m8n8.x4.shared.b16 {%0,%1,%2,%3}, [%4];"
                 : "=r"(r0), "=r"(r1), "=r"(r2), "=r"(r3) : "r"(a));
}

__device__ __forceinline__ void mma_f16(float& c0, float& c1, float& c2, float& c3,
                                        unsigned a0, unsigned a1, unsigned a2, unsigned a3,
                                        unsigned b0, unsigned b1) {
    asm volatile(
        "mma.sync.aligned.m16n8k16.row.col.f32.f16.f16.f32 "
        "{%0,%1,%2,%3}, {%4,%5,%6,%7}, {%8,%9}, {%0,%1,%2,%3};"
        : "+f"(c0), "+f"(c1), "+f"(c2), "+f"(c3)
        : "r"(a0), "r"(a1), "r"(a2), "r"(a3), "r"(b0), "r"(b1));
}

// ---------------- kernel 0: pack W only (1.5 MB one-time; feat split stays fused) ----------------
__global__ __launch_bounds__(256) void prep_w(const float* __restrict__ Wq,
                                              const float* __restrict__ Wk,
                                              const float* __restrict__ Wv) {
    const int j = blockIdx.x * 256 + threadIdx.x;
    const int WSZ = (DIN / 2) * DHEAD;
    if (j < 3 * WSZ) {
        int mat = j / WSZ;
        int r = j - mat * WSZ;
        int k2 = r / DHEAD, n = r % DHEAD;
        const float* __restrict__ W = (mat == 0) ? Wq : ((mat == 1) ? Wk : Wv);
        g_Wp[j] = __halves2half2(__float2half_rn(W[(size_t)(2 * k2) * DHEAD + n]),
                                 __float2half_rn(W[(size_t)(2 * k2 + 1) * DHEAD + n]));
    }
}

// ---------------- kernel 1: QKV projection, fp16 x2 (split-A in-kernel), packed-W B ----------------
__global__ __launch_bounds__(256) void proj_kernel(const float* __restrict__ feat) {
    __shared__ __half2 As[2][128][8];   // [hi/lo][row][k2 ^ (row&7)]
    __shared__ __half2 Bs[128][8];      // [col][k2 ^ (col&7)]

    const int tid = threadIdx.x;
    const int w = tid >> 5, lane = tid & 31, g = lane >> 2, t = lane & 3;
    const int wm = w >> 1, wn = w & 1;
    const int m0 = blockIdx.x * 128;
    const int n0 = blockIdx.y * 128;
    const int mat = blockIdx.z;
    const __half2* __restrict__ Wp = &g_Wp[mat * (DIN / 2) * DHEAD];

    float acc[2][8][4];
#pragma unroll
    for (int mt = 0; mt < 2; mt++)
#pragma unroll
        for (int nt = 0; nt < 8; nt++)
#pragma unroll
            for (int j = 0; j < 4; j++) acc[mt][nt][j] = 0.f;

    for (int kb = 0; kb < DIN; kb += 16) {
        // A tile [128][16]: fp32 load, hi/lo split (fused — feat slice reused from L2 by 6 CTAs)
#pragma unroll
        for (int i = 0; i < 2; i++) {
            int e = tid + 256 * i;
            int r = e >> 2, c = (e & 3) << 2;
            float4 v = *(const float4*)&feat[(size_t)(m0 + r) * DIN + kb + c];
            __half hx = __float2half_rn(v.x), hy = __float2half_rn(v.y);
            __half hz = __float2half_rn(v.z), hw = __float2half_rn(v.w);
            __half lx = __float2half_rn(v.x - __half2float(hx));
            __half ly = __float2half_rn(v.y - __half2float(hy));
            __half lz = __float2half_rn(v.z - __half2float(hz));
            __half lw = __float2half_rn(v.w - __half2float(hw));
            int p0 = c >> 1, rm = r & 7;
            As[0][r][p0 ^ rm] = __halves2half2(hx, hy);
            As[0][r][(p0 + 1) ^ rm] = __halves2half2(hz, hw);
            As[1][r][p0 ^ rm] = __halves2half2(lx, ly);
            As[1][r][(p0 + 1) ^ rm] = __halves2half2(lz, lw);
        }
        // B tile: conversion-free from packed W
#pragma unroll
        for (int i = 0; i < 4; i++) {
            int idx = tid + 256 * i;
            int n = idx & 127, k2l = idx >> 7;
            Bs[n][k2l ^ (n & 7)] = Wp[(size_t)(kb / 2 + k2l) * DHEAD + n0 + n];
        }
        __syncthreads();

        unsigned b[8][2];
#pragma unroll
        for (int nt = 0; nt < 8; nt++) {
            int n = 64 * wn + 8 * nt + g, nm = n & 7;
            b[nt][0] = *(const unsigned*)&Bs[n][t ^ nm];
            b[nt][1] = *(const unsigned*)&Bs[n][(t + 4) ^ nm];
        }
#pragma unroll
        for (int sp = 0; sp < 2; sp++) {
#pragma unroll
            for (int mt = 0; mt < 2; mt++) {
                int r = 32 * wm + 16 * mt + g, rm = r & 7;
                unsigned a0 = *(const unsigned*)&As[sp][r][t ^ rm];
                unsigned a1 = *(const unsigned*)&As[sp][r + 8][t ^ rm];
                unsigned a2 = *(const unsigned*)&As[sp][r][(t + 4) ^ rm];
                unsigned a3 = *(const unsigned*)&As[sp][r + 8][(t + 4) ^ rm];
#pragma unroll
                for (int nt = 0; nt < 8; nt++)
                    mma_f16(acc[mt][nt][0], acc[mt][nt][1], acc[mt][nt][2], acc[mt][nt][3],
                            a0, a1, a2, a3, b[nt][0], b[nt][1]);
            }
        }
        __syncthreads();
    }

    const float scale = (mat == 0) ? 0.0625f : 1.0f;
#pragma unroll
    for (int mt = 0; mt < 2; mt++) {
        int r = m0 + 32 * wm + 16 * mt + g;
#pragma unroll
        for (int nt = 0; nt < 8; nt++) {
            int col = n0 + 64 * wn + 8 * nt + 2 * t;
            __half h00 = __float2half_rn(acc[mt][nt][0] * scale);
            __half h01 = __float2half_rn(acc[mt][nt][1] * scale);
            __half h10 = __float2half_rn(acc[mt][nt][2] * scale);
            __half h11 = __float2half_rn(acc[mt][nt][3] * scale);
            if (mat == 2) {
                g_Vt[(size_t)col * NTOK + r] = h00;
                g_Vt[(size_t)(col + 1) * NTOK + r] = h01;
                g_Vt[(size_t)col * NTOK + r + 8] = h10;
                g_Vt[(size_t)(col + 1) * NTOK + r + 8] = h11;
            } else {
                __half* dst = (mat == 0) ? g_Qh : g_Kh;
                *(__half2*)&dst[(size_t)r * DHEAD + col] = __halves2half2(h00, h01);
                *(__half2*)&dst[(size_t)(r + 8) * DHEAD + col] = __halves2half2(h10, h11);
            }
        }
    }
}

// ---------------- kernel 2: pipelined fp16 attention (R7 structure + pair barrier) ----------------
// SMEM layout (bytes):
#define SMO_Q   0u        // [128][256] half, row stride 512B, 16B-granule xor swizzle
#define SMO_K0  65536u    // [64][256] half
#define SMO_K1  98304u
#define SMO_V   131072u   // [256][64] half (V^T), row stride 128B
#define SMO_C   163840u   // [128][64] float (cnt), row stride 256B
#define SMO_P   196608u   // [128] rows x 144B, linear
#define SMO_L   215040u   // 256 floats
#define SMEM_DYN (215040u + 1024u)

__global__ __launch_bounds__(256, 1) void attn_kernel(const float* __restrict__ cnt) {
    extern __shared__ char sm[];
    const uint32_t sb = smem_u32(sm);

    const int tid = threadIdx.x, w = tid >> 5, lane = tid & 31;
    const int g = lane >> 2, t = lane & 3;
    const int wm = w & 3, wh = w >> 2;     // 4 m-warps x 2 n/d-half warps
    const int m0 = blockIdx.x * BM;
    const int sp = blockIdx.y;
    const int jb0 = sp * (NTOK / NSPLIT);

    // ldmatrix lane decomposition
    const int lr = lane & 7;
    const int lm = (lane >> 3) & 1;
    const int lh = lane >> 4;

    const int ar0 = 32 * wm + lr + 8 * lm;
    const uint32_t qb0 = sb + SMO_Q + (uint32_t)ar0 * 512u;
    const uint32_t qb1 = qb0 + 16u * 512u;
    const uint32_t pb0 = sb + SMO_P + (uint32_t)ar0 * 144u;
    const uint32_t pb1 = pb0 + 16u * 144u;
    const int bnr = lr + 8 * lh;
    const uint32_t kroff = (uint32_t)(32 * wh + bnr) * 512u;
    const uint32_t vb = sb + SMO_V + (uint32_t)(128 * wh + bnr) * 128u;

    // ---- prologue: Q tile + K_0 via cp.async (group 0) ----
#pragma unroll
    for (int i = 0; i < 16; i++) {
        int e = tid + 256 * i;
        int r = e >> 5, blk = e & 31;
        uint32_t d = sb + SMO_Q + (uint32_t)r * 512u + (uint32_t)((blk ^ (r & 7)) << 4);
        cp16(d, &g_Qh[(size_t)(m0 + r) * DHEAD + 8 * blk]);
    }
#pragma unroll
    for (int i = 0; i < 8; i++) {
        int e = tid + 256 * i;
        int r = e >> 5, blk = e & 31;
        uint32_t d = sb + SMO_K0 + (uint32_t)r * 512u + (uint32_t)((blk ^ (r & 7)) << 4);
        cp16(d, &g_Kh[(size_t)(jb0 + r) * DHEAD + 8 * blk]);
    }
    CP_COMMIT();

    float O[2][16][4];
#pragma unroll
    for (int mt = 0; mt < 2; mt++)
#pragma unroll
        for (int nt = 0; nt < 16; nt++)
#pragma unroll
            for (int q = 0; q < 4; q++) O[mt][nt][q] = 0.f;
    float lA[2] = {0.f, 0.f}, lB[2] = {0.f, 0.f};

    const int rA0 = 32 * wm + g, rB0 = rA0 + 8;

    for (int j = 0; j < JBLOCKS; j++) {
        const int jb = jb0 + j * BN;
        __syncthreads();   // barrier 1 (full): prev AV done with V/P/C; K[(j+1)&1] free

        // ---- issue V_j + C_j (one group) ----
#pragma unroll
        for (int i = 0; i < 8; i++) {
            int e = tid + 256 * i;
            int dd = e >> 3, blk = e & 7;
            uint32_t d = sb + SMO_V + (uint32_t)dd * 128u + (uint32_t)((blk ^ (dd & 7)) << 4);
            cp16(d, &g_Vt[(size_t)dd * NTOK + jb + 8 * blk]);
        }
#pragma unroll
        for (int i = 0; i < 8; i++) {
            int e = tid + 256 * i;
            int r = e >> 4, blk = e & 15;
            uint32_t d = sb + SMO_C + (uint32_t)r * 256u +
                         (uint32_t)(((4 * blk) ^ ((r & 7) << 2)) << 2);
            cp16(d, &cnt[(size_t)(m0 + r) * NTOK + jb + 4 * blk]);
        }
        CP_COMMIT();

        // ---- issue K_{j+1} ----
        if (j + 1 < JBLOCKS) {
            uint32_t kb = ((j + 1) & 1) ? SMO_K1 : SMO_K0;
#pragma unroll
            for (int i = 0; i < 8; i++) {
                int e = tid + 256 * i;
                int r = e >> 5, blk = e & 31;
                uint32_t d = sb + kb + (uint32_t)r * 512u + (uint32_t)((blk ^ (r & 7)) << 4);
                cp16(d, &g_Kh[(size_t)(jb + BN + r) * DHEAD + 8 * blk]);
            }
        }
        CP_COMMIT();

        CP_WAIT(2);        // K_j (and Q on j=0) complete
        __syncthreads();   // barrier 2 (full): K visible

        // ---- QK_j : warp computes S[32 rows x 32 cols], k = 256 via ldmatrix ----
        const uint32_t kbuf = sb + ((j & 1) ? SMO_K1 : SMO_K0) + kroff;
        float S[2][4][4];
#pragma unroll
        for (int mt = 0; mt < 2; mt++)
#pragma unroll
            for (int nt = 0; nt < 4; nt++)
#pragma unroll
                for (int q = 0; q < 4; q++) S[mt][nt][q] = 0.f;

#pragma unroll 4
        for (int s = 0; s < 16; s++) {
            const uint32_t xa = (uint32_t)(((2 * s + lh) ^ lr) << 4);
            const uint32_t xb = (uint32_t)(((2 * s + lm) ^ lr) << 4);
            unsigned a0[4], a1[4], b0[4], b1[4];
            ldsm4(a0[0], a0[1], a0[2], a0[3], qb0 + xa);
            ldsm4(a1[0], a1[1], a1[2], a1[3], qb1 + xa);
            ldsm4(b0[0], b0[1], b0[2], b0[3], kbuf + xb);
            ldsm4(b1[0], b1[1], b1[2], b1[3], kbuf + 16u * 512u + xb);
            mma_f16(S[0][0][0], S[0][0][1], S[0][0][2], S[0][0][3], a0[0], a0[1], a0[2], a0[3], b0[0], b0[1]);
            mma_f16(S[0][1][0], S[0][1][1], S[0][1][2], S[0][1][3], a0[0], a0[1], a0[2], a0[3], b0[2], b0[3]);
            mma_f16(S[0][2][0], S[0][2][1], S[0][2][2], S[0][2][3], a0[0], a0[1], a0[2], a0[3], b1[0], b1[1]);
            mma_f16(S[0][3][0], S[0][3][1], S[0][3][2], S[0][3][3], a0[0], a0[1], a0[2], a0[3], b1[2], b1[3]);
            mma_f16(S[1][0][0], S[1][0][1], S[1][0][2], S[1][0][3], a1[0], a1[1], a1[2], a1[3], b0[0], b0[1]);
            mma_f16(S[1][1][0], S[1][1][1], S[1][1][2], S[1][1][3], a1[0], a1[1], a1[2], a1[3], b0[2], b0[3]);
            mma_f16(S[1][2][0], S[1][2][1], S[1][2][2], S[1][2][3], a1[0], a1[1], a1[2], a1[3], b1[0], b1[1]);
            mma_f16(S[1][3][0], S[1][3][1], S[1][3][2], S[1][3][3], a1[0], a1[1], a1[2], a1[3], b1[2], b1[3]);
        }

        CP_WAIT(1);        // V_j + C_j complete (K_{j+1} may still fly)
        __syncthreads();   // barrier 3 (full): V + cnt visible to all

        // ---- epilogue: P = exp(S) * cnt -> Ps (fp16), accumulate l ----
        const char* Cs = sm + SMO_C;
        char* Ps = sm + SMO_P;
#pragma unroll
        for (int mt = 0; mt < 2; mt++) {
            int rA = rA0 + 16 * mt, rB = rB0 + 16 * mt;
            float sA = 0.f, sB = 0.f;
#pragma unroll
            for (int nt = 0; nt < 4; nt++) {
                int ci = ((32 * wh + 8 * nt + 2 * t) ^ (g << 2)) << 2;
                float2 cA = *(const float2*)(Cs + rA * 256 + ci);
                float2 cB = *(const float2*)(Cs + rB * 256 + ci);
                float p0 = __expf(S[mt][nt][0]) * cA.x;
                float p1 = __expf(S[mt][nt][1]) * cA.y;
                float p2 = __expf(S[mt][nt][2]) * cB.x;
                float p3 = __expf(S[mt][nt][3]) * cB.y;
                sA += p0 + p1;
                sB += p2 + p3;
                int q = (16 * wh + 4 * nt + t) << 2;
                *(__half2*)(Ps + rA * 144 + q) = __halves2half2(__float2half_rn(p0), __float2half_rn(p1));
                *(__half2*)(Ps + rB * 144 + q) = __halves2half2(__float2half_rn(p2), __float2half_rn(p3));
            }
            sA += __shfl_xor_sync(0xffffffffu, sA, 1);
            sA += __shfl_xor_sync(0xffffffffu, sA, 2);
            sB += __shfl_xor_sync(0xffffffffu, sB, 1);
            sB += __shfl_xor_sync(0xffffffffu, sB, 2);
            lA[mt] += sA;
            lB[mt] += sB;
        }
        // barrier 4 (PAIR): AV for warp (wm,wh) reads P rows [32wm,32wm+32) and those rows
        // are written only by warps (wm,0) and (wm,1). V is already visible via barrier 3.
        // Cross-iteration P reuse is guarded by barrier 1. So a 2-warp named barrier suffices.
        asm volatile("bar.sync %0, 64;" :: "r"(wm + 1) : "memory");

        // ---- AV_j : O[32 rows x 128 cols] += P @ V^T, k = 64 via ldmatrix ----
#pragma unroll
        for (int s = 0; s < 4; s++) {
            const uint32_t xp = (uint32_t)((2 * s + lh) << 4);
            const uint32_t xv = (uint32_t)(((2 * s + lm) ^ lr) << 4);
            unsigned pa0[4], pa1[4];
            ldsm4(pa0[0], pa0[1], pa0[2], pa0[3], pb0 + xp);
            ldsm4(pa1[0], pa1[1], pa1[2], pa1[3], pb1 + xp);
#pragma unroll
            for (int p = 0; p < 8; p++) {
                unsigned vv[4];
                ldsm4(vv[0], vv[1], vv[2], vv[3], vb + (uint32_t)p * 2048u + xv);
                mma_f16(O[0][2 * p][0], O[0][2 * p][1], O[0][2 * p][2], O[0][2 * p][3],
                        pa0[0], pa0[1], pa0[2], pa0[3], vv[0], vv[1]);
                mma_f16(O[0][2 * p + 1][0], O[0][2 * p + 1][1], O[0][2 * p + 1][2], O[0][2 * p + 1][3],
                        pa0[0], pa0[1], pa0[2], pa0[3], vv[2], vv[3]);
                mma_f16(O[1][2 * p][0], O[1][2 * p][1], O[1][2 * p][2], O[1][2 * p][3],
                        pa1[0], pa1[1], pa1[2], pa1[3], vv[0], vv[1]);
                mma_f16(O[1][2 * p + 1][0], O[1][2 * p + 1][1], O[1][2 * p + 1][2], O[1][2 * p + 1][3],
                        pa1[0], pa1[1], pa1[2], pa1[3], vv[2], vv[3]);
            }
        }
    }

    // ---- O writeout ----
#pragma unroll
    for (int mt = 0; mt < 2; mt++) {
        int rA = m0 + rA0 + 16 * mt, rB = m0 + rB0 + 16 * mt;
#pragma unroll
        for (int nt = 0; nt < 16; nt++) {
            int col = 128 * wh + 8 * nt + 2 * t;
            *(float2*)&g_Op[sp][rA][col] = make_float2(O[mt][nt][0], O[mt][nt][1]);
            *(float2*)&g_Op[sp][rB][col] = make_float2(O[mt][nt][2], O[mt][nt][3]);
        }
    }

    // ---- l reduce across the two wh warps ----
    float* Lr = (float*)(sm + SMO_L);
    if (t == 0) {
#pragma unroll
        for (int mt = 0; mt < 2; mt++) {
            Lr[wh * 128 + rA0 + 16 * mt] = lA[mt];
            Lr[wh * 128 + rB0 + 16 * mt] = lB[mt];
        }
    }
    __syncthreads();
    if (tid < 128) g_ls[sp][m0 + tid] = Lr[tid] + Lr[128 + tid];
}

// ---------------- kernel 3: combine + ELU (float2, 4096 blocks) ----------------
__global__ __launch_bounds__(256) void combine_kernel(float* __restrict__ out) {
    const int idx = blockIdx.x * 256 + threadIdx.x;     // 1M float2 total
    const int row = idx >> 7;
    const int d2 = (idx & 127) << 1;
    float2 n0 = *(const float2*)&g_Op[0][row][d2];
    float2 n1 = *(const float2*)&g_Op[1][row][d2];
    float den = g_ls[0][row] + g_ls[1][row];
    float inv = 1.0f / den;
    float r0 = (n0.x + n1.x) * inv;
    float r1 = (n0.y + n1.y) * inv;
    float2 o;
    o.x = (r0 > 0.f) ? r0 : expm1f(r0);
    o.y = (r1 > 0.f) ? r1 : expm1f(r1);
    *(float2*)&out[(size_t)row * DHEAD + d2] = o;
}

// ---------------- launch ----------------
extern "C" void kernel_launch(void* const* d_in, const int* in_sizes, int n_in,
                              void* d_out, int out_size) {
    (void)in_sizes; (void)n_in; (void)out_size;
    const float* feat = (const float*)d_in[0];
    const float* cnt = (const float*)d_in[1];
    const float* Wq = (const float*)d_in[2];
    const float* Wk = (const float*)d_in[3];
    const float* Wv = (const float*)d_in[4];

    prep_w<<<(3 * (DIN / 2) * DHEAD + 255) / 256, 256>>>(Wq, Wk, Wv);

    proj_kernel<<<dim3(NTOK / 128, DHEAD / 128, 3), 256>>>(feat);

    cudaFuncSetAttribute(attn_kernel, cudaFuncAttributeMaxDynamicSharedMemorySize, (int)SMEM_DYN);
    attn_kernel<<<dim3(NTOK / BM, NSPLIT), 256, SMEM_DYN>>>(cnt);

    combine_kernel<<<NTOK * DHEAD / 512, 256>>>((float*)d_out);
}

// round 10
// speedup vs baseline: 1.2046x; 1.0072x over previous
#include <cuda_runtime.h>
#include <cuda_fp16.h>
#include <cstdint>

#define NTOK 8192
#define DIN  512
#define DHEAD 256
#define NSPLIT 2
#define BM 128
#define BN 64
#define JBLOCKS (NTOK / NSPLIT / BN)   // 64

// ---------------- scratch ----------------
__device__ __half2 g_Wp[3 * (DIN / 2) * DHEAD];  // W packed as k-pairs, fp16
__device__ __half  g_Qh[NTOK * DHEAD];        // fp16, pre-scaled by 1/16
__device__ __half  g_Kh[NTOK * DHEAD];        // fp16
__device__ __half  g_Vt[DHEAD * NTOK];        // V transposed [d][tok], fp16
__device__ float   g_Op[NSPLIT][NTOK][DHEAD];
__device__ float   g_ls[NSPLIT][NTOK];

// ---------------- helpers ----------------
__device__ __forceinline__ uint32_t smem_u32(const void* p) {
    uint32_t a;
    asm("{ .reg .u64 t; cvta.to.shared.u64 t, %1; cvt.u32.u64 %0, t; }" : "=r"(a) : "l"(p));
    return a;
}
__device__ __forceinline__ void cp16(uint32_t dst, const void* src) {
    asm volatile("cp.async.cg.shared.global [%0], [%1], 16;" :: "r"(dst), "l"(src));
}
#define CP_COMMIT() asm volatile("cp.async.commit_group;" ::: "memory")
#define CP_WAIT(n)  asm volatile("cp.async.wait_group %0;" :: "n"(n) : "memory")

__device__ __forceinline__ void ldsm4(unsigned& r0, unsigned& r1, unsigned& r2, unsigned& r3,
                                      uint32_t a) {
    asm volatile("ldmatrix.sync.aligned.m8n8.x4.shared.b16 {%0,%1,%2,%3}, [%4];"
                 : "=r"(r0), "=r"(r1), "=r"(r2), "=r"(r3) : "r"(a));
}

__device__ __forceinline__ void mma_f16(float& c0, float& c1, float& c2, float& c3,
                                        unsigned a0, unsigned a1, unsigned a2, unsigned a3,
                                        unsigned b0, unsigned b1) {
    asm volatile(
        "mma.sync.aligned.m16n8k16.row.col.f32.f16.f16.f32 "
        "{%0,%1,%2,%3}, {%4,%5,%6,%7}, {%8,%9}, {%0,%1,%2,%3};"
        : "+f"(c0), "+f"(c1), "+f"(c2), "+f"(c3)
        : "r"(a0), "r"(a1), "r"(a2), "r"(a3), "r"(b0), "r"(b1));
}

__device__ __forceinline__ unsigned pack_hi(float a, float b) {
    __half2 h = __halves2half2(__float2half_rn(a), __float2half_rn(b));
    return *(unsigned*)&h;
}
__device__ __forceinline__ unsigned pack_lo(float a, float b) {
    float ra = a - __half2float(__float2half_rn(a));
    float rb = b - __half2float(__float2half_rn(b));
    __half2 h = __halves2half2(__float2half_rn(ra), __float2half_rn(rb));
    return *(unsigned*)&h;
}

// ---------------- kernel 0: pack W (1.5 MB one-time) ----------------
__global__ __launch_bounds__(256) void prep_w(const float* __restrict__ Wq,
                                              const float* __restrict__ Wk,
                                              const float* __restrict__ Wv) {
    const int j = blockIdx.x * 256 + threadIdx.x;
    const int WSZ = (DIN / 2) * DHEAD;
    if (j < 3 * WSZ) {
        int mat = j / WSZ;
        int r = j - mat * WSZ;
        int k2 = r / DHEAD, n = r % DHEAD;
        const float* __restrict__ W = (mat == 0) ? Wq : ((mat == 1) ? Wk : Wv);
        g_Wp[j] = __halves2half2(__float2half_rn(W[(size_t)(2 * k2) * DHEAD + n]),
                                 __float2half_rn(W[(size_t)(2 * k2 + 1) * DHEAD + n]));
    }
}

// ---------------- kernel 1: QKV projection v2 — pipelined, k-tile 32 ----------------
// Smem layout: rows of 16 half2 (4 x 16B chunks), physical chunk = logical ^ ((row>>1)&3).
// All fragment LDS are bank-bijective; all stores are STS.128.
__global__ __launch_bounds__(256) void proj_kernel(const float* __restrict__ feat) {
    __shared__ __align__(16) __half2 As[2][128][16];   // [hi/lo][row][swizzled k2]
    __shared__ __align__(16) __half2 Bs[128][16];      // [col][swizzled k2]

    const int tid = threadIdx.x;
    const int w = tid >> 5, lane = tid & 31, g = lane >> 2, t = lane & 3;
    const int wm = w >> 1, wn = w & 1;
    const int m0 = blockIdx.x * 128;
    const int n0 = blockIdx.y * 128;
    const int mat = blockIdx.z;
    const __half2* __restrict__ Wp = &g_Wp[mat * (DIN / 2) * DHEAD];

    // load-thread mapping
    const int ar = tid >> 1;             // A row 0..127
    const int ak = (tid & 1) << 4;       // k offset in halfs (0 / 16)
    const int acb = (tid & 1) << 1;      // A logical chunk base (0 / 2)
    const int aq = (ar >> 1) & 3;
    const int bn = tid & 127;            // B col
    const int bcb = (tid >> 7) << 1;     // B logical chunk base (0 / 2)
    const int bq = (bn >> 1) & 3;

    float4 aR[4];
    unsigned bR[8];

    {   // prologue: load tile 0
        const float* ap = &feat[(size_t)(m0 + ar) * DIN + ak];
        aR[0] = *(const float4*)(ap);
        aR[1] = *(const float4*)(ap + 4);
        aR[2] = *(const float4*)(ap + 8);
        aR[3] = *(const float4*)(ap + 12);
        const __half2* bp = &Wp[(size_t)(bcb * 4) * DHEAD + n0 + bn];
#pragma unroll
        for (int jj = 0; jj < 8; jj++) bR[jj] = *(const unsigned*)&bp[(size_t)jj * DHEAD];
    }

    float acc[2][8][4];
#pragma unroll
    for (int mt = 0; mt < 2; mt++)
#pragma unroll
        for (int nt = 0; nt < 8; nt++)
#pragma unroll
            for (int q = 0; q < 4; q++) acc[mt][nt][q] = 0.f;

    for (int it = 0; it < 16; it++) {
        // ---- store prefetched tile (convert A to hi/lo) ----
        {
            uint4 hq0, hq1, lq0, lq1;
            hq0.x = pack_hi(aR[0].x, aR[0].y); hq0.y = pack_hi(aR[0].z, aR[0].w);
            hq0.z = pack_hi(aR[1].x, aR[1].y); hq0.w = pack_hi(aR[1].z, aR[1].w);
            hq1.x = pack_hi(aR[2].x, aR[2].y); hq1.y = pack_hi(aR[2].z, aR[2].w);
            hq1.z = pack_hi(aR[3].x, aR[3].y); hq1.w = pack_hi(aR[3].z, aR[3].w);
            lq0.x = pack_lo(aR[0].x, aR[0].y); lq0.y = pack_lo(aR[0].z, aR[0].w);
            lq0.z = pack_lo(aR[1].x, aR[1].y); lq0.w = pack_lo(aR[1].z, aR[1].w);
            lq1.x = pack_lo(aR[2].x, aR[2].y); lq1.y = pack_lo(aR[2].z, aR[2].w);
            lq1.z = pack_lo(aR[3].x, aR[3].y); lq1.w = pack_lo(aR[3].z, aR[3].w);
            *(uint4*)&As[0][ar][((acb    ) ^ aq) << 2] = hq0;
            *(uint4*)&As[0][ar][((acb + 1) ^ aq) << 2] = hq1;
            *(uint4*)&As[1][ar][((acb    ) ^ aq) << 2] = lq0;
            *(uint4*)&As[1][ar][((acb + 1) ^ aq) << 2] = lq1;
            uint4 bq0, bq1;
            bq0.x = bR[0]; bq0.y = bR[1]; bq0.z = bR[2]; bq0.w = bR[3];
            bq1.x = bR[4]; bq1.y = bR[5]; bq1.z = bR[6]; bq1.w = bR[7];
            *(uint4*)&Bs[bn][((bcb    ) ^ bq) << 2] = bq0;
            *(uint4*)&Bs[bn][((bcb + 1) ^ bq) << 2] = bq1;
        }
        __syncthreads();

        // ---- prefetch tile it+1 (LDG latency hides under compute) ----
        if (it + 1 < 16) {
            const int kb = (it + 1) << 5;
            const float* ap = &feat[(size_t)(m0 + ar) * DIN + kb + ak];
            aR[0] = *(const float4*)(ap);
            aR[1] = *(const float4*)(ap + 4);
            aR[2] = *(const float4*)(ap + 8);
            aR[3] = *(const float4*)(ap + 12);
            const __half2* bp = &Wp[(size_t)(kb / 2 + bcb * 4) * DHEAD + n0 + bn];
#pragma unroll
            for (int jj = 0; jj < 8; jj++) bR[jj] = *(const unsigned*)&bp[(size_t)jj * DHEAD];
        }

        // ---- compute: 2 k16-steps x (2sp x 2mt x 8nt) mma ----
#pragma unroll
        for (int ks = 0; ks < 2; ks++) {
            unsigned bfr[8][2];
#pragma unroll
            for (int nt = 0; nt < 8; nt++) {
                int n = 64 * wn + 8 * nt + g;
                int qn = (n >> 1) & 3;
                bfr[nt][0] = *(const unsigned*)&Bs[n][(((2 * ks    ) ^ qn) << 2) + t];
                bfr[nt][1] = *(const unsigned*)&Bs[n][(((2 * ks + 1) ^ qn) << 2) + t];
            }
#pragma unroll
            for (int sp = 0; sp < 2; sp++) {
#pragma unroll
                for (int mt = 0; mt < 2; mt++) {
                    int r = 32 * wm + 16 * mt + g;
                    int qr = (r >> 1) & 3;   // (r+8) has the same q
                    unsigned a0 = *(const unsigned*)&As[sp][r    ][(((2 * ks    ) ^ qr) << 2) + t];
                    unsigned a1 = *(const unsigned*)&As[sp][r + 8][(((2 * ks    ) ^ qr) << 2) + t];
                    unsigned a2 = *(const unsigned*)&As[sp][r    ][(((2 * ks + 1) ^ qr) << 2) + t];
                    unsigned a3 = *(const unsigned*)&As[sp][r + 8][(((2 * ks + 1) ^ qr) << 2) + t];
#pragma unroll
                    for (int nt = 0; nt < 8; nt++)
                        mma_f16(acc[mt][nt][0], acc[mt][nt][1], acc[mt][nt][2], acc[mt][nt][3],
                                a0, a1, a2, a3, bfr[nt][0], bfr[nt][1]);
                }
            }
        }
        __syncthreads();
    }

    const float scale = (mat == 0) ? 0.0625f : 1.0f;
#pragma unroll
    for (int mt = 0; mt < 2; mt++) {
        int r = m0 + 32 * wm + 16 * mt + g;
#pragma unroll
        for (int nt = 0; nt < 8; nt++) {
            int col = n0 + 64 * wn + 8 * nt + 2 * t;
            __half h00 = __float2half_rn(acc[mt][nt][0] * scale);
            __half h01 = __float2half_rn(acc[mt][nt][1] * scale);
            __half h10 = __float2half_rn(acc[mt][nt][2] * scale);
            __half h11 = __float2half_rn(acc[mt][nt][3] * scale);
            if (mat == 2) {
                g_Vt[(size_t)col * NTOK + r] = h00;
                g_Vt[(size_t)(col + 1) * NTOK + r] = h01;
                g_Vt[(size_t)col * NTOK + r + 8] = h10;
                g_Vt[(size_t)(col + 1) * NTOK + r + 8] = h11;
            } else {
                __half* dst = (mat == 0) ? g_Qh : g_Kh;
                *(__half2*)&dst[(size_t)r * DHEAD + col] = __halves2half2(h00, h01);
                *(__half2*)&dst[(size_t)(r + 8) * DHEAD + col] = __halves2half2(h10, h11);
            }
        }
    }
}

// ---------------- kernel 2: pipelined fp16 attention (R9 + full QK unroll) ----------------
#define SMO_Q   0u
#define SMO_K0  65536u
#define SMO_K1  98304u
#define SMO_V   131072u
#define SMO_C   163840u
#define SMO_P   196608u
#define SMO_L   215040u
#define SMEM_DYN (215040u + 1024u)

__global__ __launch_bounds__(256, 1) void attn_kernel(const float* __restrict__ cnt) {
    extern __shared__ char sm[];
    const uint32_t sb = smem_u32(sm);

    const int tid = threadIdx.x, w = tid >> 5, lane = tid & 31;
    const int g = lane >> 2, t = lane & 3;
    const int wm = w & 3, wh = w >> 2;
    const int m0 = blockIdx.x * BM;
    const int sp = blockIdx.y;
    const int jb0 = sp * (NTOK / NSPLIT);

    const int lr = lane & 7;
    const int lm = (lane >> 3) & 1;
    const int lh = lane >> 4;

    const int ar0 = 32 * wm + lr + 8 * lm;
    const uint32_t qb0 = sb + SMO_Q + (uint32_t)ar0 * 512u;
    const uint32_t qb1 = qb0 + 16u * 512u;
    const uint32_t pb0 = sb + SMO_P + (uint32_t)ar0 * 144u;
    const uint32_t pb1 = pb0 + 16u * 144u;
    const int bnr = lr + 8 * lh;
    const uint32_t kroff = (uint32_t)(32 * wh + bnr) * 512u;
    const uint32_t vb = sb + SMO_V + (uint32_t)(128 * wh + bnr) * 128u;

#pragma unroll
    for (int i = 0; i < 16; i++) {
        int e = tid + 256 * i;
        int r = e >> 5, blk = e & 31;
        uint32_t d = sb + SMO_Q + (uint32_t)r * 512u + (uint32_t)((blk ^ (r & 7)) << 4);
        cp16(d, &g_Qh[(size_t)(m0 + r) * DHEAD + 8 * blk]);
    }
#pragma unroll
    for (int i = 0; i < 8; i++) {
        int e = tid + 256 * i;
        int r = e >> 5, blk = e & 31;
        uint32_t d = sb + SMO_K0 + (uint32_t)r * 512u + (uint32_t)((blk ^ (r & 7)) << 4);
        cp16(d, &g_Kh[(size_t)(jb0 + r) * DHEAD + 8 * blk]);
    }
    CP_COMMIT();

    float O[2][16][4];
#pragma unroll
    for (int mt = 0; mt < 2; mt++)
#pragma unroll
        for (int nt = 0; nt < 16; nt++)
#pragma unroll
            for (int q = 0; q < 4; q++) O[mt][nt][q] = 0.f;
    float lA[2] = {0.f, 0.f}, lB[2] = {0.f, 0.f};

    const int rA0 = 32 * wm + g, rB0 = rA0 + 8;

    for (int j = 0; j < JBLOCKS; j++) {
        const int jb = jb0 + j * BN;
        __syncthreads();   // barrier 1: prev AV done with V/P/C; K[(j+1)&1] free

#pragma unroll
        for (int i = 0; i < 8; i++) {
            int e = tid + 256 * i;
            int dd = e >> 3, blk = e & 7;
            uint32_t d = sb + SMO_V + (uint32_t)dd * 128u + (uint32_t)((blk ^ (dd & 7)) << 4);
            cp16(d, &g_Vt[(size_t)dd * NTOK + jb + 8 * blk]);
        }
#pragma unroll
        for (int i = 0; i < 8; i++) {
            int e = tid + 256 * i;
            int r = e >> 4, blk = e & 15;
            uint32_t d = sb + SMO_C + (uint32_t)r * 256u +
                         (uint32_t)(((4 * blk) ^ ((r & 7) << 2)) << 2);
            cp16(d, &cnt[(size_t)(m0 + r) * NTOK + jb + 4 * blk]);
        }
        CP_COMMIT();

        if (j + 1 < JBLOCKS) {
            uint32_t kb = ((j + 1) & 1) ? SMO_K1 : SMO_K0;
#pragma unroll
            for (int i = 0; i < 8; i++) {
                int e = tid + 256 * i;
                int r = e >> 5, blk = e & 31;
                uint32_t d = sb + kb + (uint32_t)r * 512u + (uint32_t)((blk ^ (r & 7)) << 4);
                cp16(d, &g_Kh[(size_t)(jb + BN + r) * DHEAD + 8 * blk]);
            }
        }
        CP_COMMIT();

        CP_WAIT(2);
        __syncthreads();   // barrier 2: K visible

        const uint32_t kbuf = sb + ((j & 1) ? SMO_K1 : SMO_K0) + kroff;
        float S[2][4][4];
#pragma unroll
        for (int mt = 0; mt < 2; mt++)
#pragma unroll
            for (int nt = 0; nt < 4; nt++)
#pragma unroll
                for (int q = 0; q < 4; q++) S[mt][nt][q] = 0.f;

#pragma unroll
        for (int s = 0; s < 16; s++) {
            const uint32_t xa = (uint32_t)(((2 * s + lh) ^ lr) << 4);
            const uint32_t xb = (uint32_t)(((2 * s + lm) ^ lr) << 4);
            unsigned a0[4], a1[4], b0[4], b1[4];
            ldsm4(a0[0], a0[1], a0[2], a0[3], qb0 + xa);
            ldsm4(a1[0], a1[1], a1[2], a1[3], qb1 + xa);
            ldsm4(b0[0], b0[1], b0[2], b0[3], kbuf + xb);
            ldsm4(b1[0], b1[1], b1[2], b1[3], kbuf + 16u * 512u + xb);
            mma_f16(S[0][0][0], S[0][0][1], S[0][0][2], S[0][0][3], a0[0], a0[1], a0[2], a0[3], b0[0], b0[1]);
            mma_f16(S[0][1][0], S[0][1][1], S[0][1][2], S[0][1][3], a0[0], a0[1], a0[2], a0[3], b0[2], b0[3]);
            mma_f16(S[0][2][0], S[0][2][1], S[0][2][2], S[0][2][3], a0[0], a0[1], a0[2], a0[3], b1[0], b1[1]);
            mma_f16(S[0][3][0], S[0][3][1], S[0][3][2], S[0][3][3], a0[0], a0[1], a0[2], a0[3], b1[2], b1[3]);
            mma_f16(S[1][0][0], S[1][0][1], S[1][0][2], S[1][0][3], a1[0], a1[1], a1[2], a1[3], b0[0], b0[1]);
            mma_f16(S[1][1][0], S[1][1][1], S[1][1][2], S[1][1][3], a1[0], a1[1], a1[2], a1[3], b0[2], b0[3]);
            mma_f16(S[1][2][0], S[1][2][1], S[1][2][2], S[1][2][3], a1[0], a1[1], a1[2], a1[3], b1[0], b1[1]);
            mma_f16(S[1][3][0], S[1][3][1], S[1][3][2], S[1][3][3], a1[0], a1[1], a1[2], a1[3], b1[2], b1[3]);
        }

        CP_WAIT(1);
        __syncthreads();   // barrier 3: V + cnt visible

        const char* Cs = sm + SMO_C;
        char* Ps = sm + SMO_P;
#pragma unroll
        for (int mt = 0; mt < 2; mt++) {
            int rA = rA0 + 16 * mt, rB = rB0 + 16 * mt;
            float sA = 0.f, sB = 0.f;
#pragma unroll
            for (int nt = 0; nt < 4; nt++) {
                int ci = ((32 * wh + 8 * nt + 2 * t) ^ (g << 2)) << 2;
                float2 cA = *(const float2*)(Cs + rA * 256 + ci);
                float2 cB = *(const float2*)(Cs + rB * 256 + ci);
                float p0 = __expf(S[mt][nt][0]) * cA.x;
                float p1 = __expf(S[mt][nt][1]) * cA.y;
                float p2 = __expf(S[mt][nt][2]) * cB.x;
                float p3 = __expf(S[mt][nt][3]) * cB.y;
                sA += p0 + p1;
                sB += p2 + p3;
                int q = (16 * wh + 4 * nt + t) << 2;
                *(__half2*)(Ps + rA * 144 + q) = __halves2half2(__float2half_rn(p0), __float2half_rn(p1));
                *(__half2*)(Ps + rB * 144 + q) = __halves2half2(__float2half_rn(p2), __float2half_rn(p3));
            }
            sA += __shfl_xor_sync(0xffffffffu, sA, 1);
            sA += __shfl_xor_sync(0xffffffffu, sA, 2);
            sB += __shfl_xor_sync(0xffffffffu, sB, 1);
            sB += __shfl_xor_sync(0xffffffffu, sB, 2);
            lA[mt] += sA;
            lB[mt] += sB;
        }
        // barrier 4 (PAIR): AV of warp (wm,wh) reads P rows [32wm,32wm+32) written only by
        // warps (wm,0),(wm,1). V visible via barrier 3; cross-iteration reuse via barrier 1.
        asm volatile("bar.sync %0, 64;" :: "r"(wm + 1) : "memory");

#pragma unroll
        for (int s = 0; s < 4; s++) {
            const uint32_t xp = (uint32_t)((2 * s + lh) << 4);
            const uint32_t xv = (uint32_t)(((2 * s + lm) ^ lr) << 4);
            unsigned pa0[4], pa1[4];
            ldsm4(pa0[0], pa0[1], pa0[2], pa0[3], pb0 + xp);
            ldsm4(pa1[0], pa1[1], pa1[2], pa1[3], pb1 + xp);
#pragma unroll
            for (int p = 0; p < 8; p++) {
                unsigned vv[4];
                ldsm4(vv[0], vv[1], vv[2], vv[3], vb + (uint32_t)p * 2048u + xv);
                mma_f16(O[0][2 * p][0], O[0][2 * p][1], O[0][2 * p][2], O[0][2 * p][3],
                        pa0[0], pa0[1], pa0[2], pa0[3], vv[0], vv[1]);
                mma_f16(O[0][2 * p + 1][0], O[0][2 * p + 1][1], O[0][2 * p + 1][2], O[0][2 * p + 1][3],
                        pa0[0], pa0[1], pa0[2], pa0[3], vv[2], vv[3]);
                mma_f16(O[1][2 * p][0], O[1][2 * p][1], O[1][2 * p][2], O[1][2 * p][3],
                        pa1[0], pa1[1], pa1[2], pa1[3], vv[0], vv[1]);
                mma_f16(O[1][2 * p + 1][0], O[1][2 * p + 1][1], O[1][2 * p + 1][2], O[1][2 * p + 1][3],
                        pa1[0], pa1[1], pa1[2], pa1[3], vv[2], vv[3]);
            }
        }
    }

#pragma unroll
    for (int mt = 0; mt < 2; mt++) {
        int rA = m0 + rA0 + 16 * mt, rB = m0 + rB0 + 16 * mt;
#pragma unroll
        for (int nt = 0; nt < 16; nt++) {
            int col = 128 * wh + 8 * nt + 2 * t;
            *(float2*)&g_Op[sp][rA][col] = make_float2(O[mt][nt][0], O[mt][nt][1]);
            *(float2*)&g_Op[sp][rB][col] = make_float2(O[mt][nt][2], O[mt][nt][3]);
        }
    }

    float* Lr = (float*)(sm + SMO_L);
    if (t == 0) {
#pragma unroll
        for (int mt = 0; mt < 2; mt++) {
            Lr[wh * 128 + rA0 + 16 * mt] = lA[mt];
            Lr[wh * 128 + rB0 + 16 * mt] = lB[mt];
        }
    }
    __syncthreads();
    if (tid < 128) g_ls[sp][m0 + tid] = Lr[tid] + Lr[128 + tid];
}

// ---------------- kernel 3: combine + ELU ----------------
__global__ __launch_bounds__(256) void combine_kernel(float* __restrict__ out) {
    const int idx = blockIdx.x * 256 + threadIdx.x;
    const int row = idx >> 7;
    const int d2 = (idx & 127) << 1;
    float2 n0 = *(const float2*)&g_Op[0][row][d2];
    float2 n1 = *(const float2*)&g_Op[1][row][d2];
    float den = g_ls[0][row] + g_ls[1][row];
    float inv = 1.0f / den;
    float r0 = (n0.x + n1.x) * inv;
    float r1 = (n0.y + n1.y) * inv;
    float2 o;
    o.x = (r0 > 0.f) ? r0 : expm1f(r0);
    o.y = (r1 > 0.f) ? r1 : expm1f(r1);
    *(float2*)&out[(size_t)row * DHEAD + d2] = o;
}

// ---------------- launch ----------------
extern "C" void kernel_launch(void* const* d_in, const int* in_sizes, int n_in,
                              void* d_out, int out_size) {
    (void)in_sizes; (void)n_in; (void)out_size;
    const float* feat = (const float*)d_in[0];
    const float* cnt = (const float*)d_in[1];
    const float* Wq = (const float*)d_in[2];
    const float* Wk = (const float*)d_in[3];
    const float* Wv = (const float*)d_in[4];

    prep_w<<<(3 * (DIN / 2) * DHEAD + 255) / 256, 256>>>(Wq, Wk, Wv);

    proj_kernel<<<dim3(NTOK / 128, DHEAD / 128, 3), 256>>>(feat);

    cudaFuncSetAttribute(attn_kernel, cudaFuncAttributeMaxDynamicSharedMemorySize, (int)SMEM_DYN);
    attn_kernel<<<dim3(NTOK / BM, NSPLIT), 256, SMEM_DYN>>>(cnt);

    combine_kernel<<<NTOK * DHEAD / 512, 256>>>((float*)d_out);
}

// round 11
// speedup vs baseline: 1.2402x; 1.0295x over previous
#include <cuda_runtime.h>
#include <cuda_fp16.h>
#include <cstdint>

#define NTOK 8192
#define DIN  512
#define DHEAD 256
#define NSPLIT 2
#define BM 128
#define BN 64
#define JBLOCKS (NTOK / NSPLIT / BN)   // 64

// ---------------- scratch ----------------
__device__ __half2 g_Wp[3 * (DIN / 2) * DHEAD];  // W packed as k-pairs, fp16
__device__ __half  g_Qh[NTOK * DHEAD];        // fp16, pre-scaled by log2e/16
__device__ __half  g_Kh[NTOK * DHEAD];        // fp16
__device__ __half  g_Vt[DHEAD * NTOK];        // V transposed [d][tok], fp16
__device__ float   g_Op[NSPLIT][NTOK][DHEAD];
__device__ float   g_ls[NSPLIT][NTOK];

// ---------------- helpers ----------------
__device__ __forceinline__ uint32_t smem_u32(const void* p) {
    uint32_t a;
    asm("{ .reg .u64 t; cvta.to.shared.u64 t, %1; cvt.u32.u64 %0, t; }" : "=r"(a) : "l"(p));
    return a;
}
__device__ __forceinline__ void cp16(uint32_t dst, const void* src) {
    asm volatile("cp.async.cg.shared.global [%0], [%1], 16;" :: "r"(dst), "l"(src));
}
#define CP_COMMIT() asm volatile("cp.async.commit_group;" ::: "memory")
#define CP_WAIT(n)  asm volatile("cp.async.wait_group %0;" :: "n"(n) : "memory")

__device__ __forceinline__ void ldsm4(unsigned& r0, unsigned& r1, unsigned& r2, unsigned& r3,
                                      uint32_t a) {
    asm volatile("ldmatrix.sync.aligned.m8n8.x4.shared.b16 {%0,%1,%2,%3}, [%4];"
                 : "=r"(r0), "=r"(r1), "=r"(r2), "=r"(r3) : "r"(a));
}

__device__ __forceinline__ void mma_f16(float& c0, float& c1, float& c2, float& c3,
                                        unsigned a0, unsigned a1, unsigned a2, unsigned a3,
                                        unsigned b0, unsigned b1) {
    asm volatile(
        "mma.sync.aligned.m16n8k16.row.col.f32.f16.f16.f32 "
        "{%0,%1,%2,%3}, {%4,%5,%6,%7}, {%8,%9}, {%0,%1,%2,%3};"
        : "+f"(c0), "+f"(c1), "+f"(c2), "+f"(c3)
        : "r"(a0), "r"(a1), "r"(a2), "r"(a3), "r"(b0), "r"(b1));
}

__device__ __forceinline__ float ex2f(float x) {
    float r; asm("ex2.approx.f32 %0, %1;" : "=f"(r) : "f"(x)); return r;
}

__device__ __forceinline__ unsigned pack_hi(float a, float b) {
    __half2 h = __halves2half2(__float2half_rn(a), __float2half_rn(b));
    return *(unsigned*)&h;
}
__device__ __forceinline__ unsigned pack_lo(float a, float b) {
    float ra = a - __half2float(__float2half_rn(a));
    float rb = b - __half2float(__float2half_rn(b));
    __half2 h = __halves2half2(__float2half_rn(ra), __float2half_rn(rb));
    return *(unsigned*)&h;
}

// ---------------- kernel 0: pack W (1.5 MB one-time) ----------------
__global__ __launch_bounds__(256) void prep_w(const float* __restrict__ Wq,
                                              const float* __restrict__ Wk,
                                              const float* __restrict__ Wv) {
    const int j = blockIdx.x * 256 + threadIdx.x;
    const int WSZ = (DIN / 2) * DHEAD;
    if (j < 3 * WSZ) {
        int mat = j / WSZ;
        int r = j - mat * WSZ;
        int k2 = r / DHEAD, n = r % DHEAD;
        const float* __restrict__ W = (mat == 0) ? Wq : ((mat == 1) ? Wk : Wv);
        g_Wp[j] = __halves2half2(__float2half_rn(W[(size_t)(2 * k2) * DHEAD + n]),
                                 __float2half_rn(W[(size_t)(2 * k2 + 1) * DHEAD + n]));
    }
}

// ---------------- kernel 1: QKV projection (pipelined, k-tile 32) ----------------
__global__ __launch_bounds__(256) void proj_kernel(const float* __restrict__ feat) {
    __shared__ __align__(16) __half2 As[2][128][16];
    __shared__ __align__(16) __half2 Bs[128][16];

    const int tid = threadIdx.x;
    const int w = tid >> 5, lane = tid & 31, g = lane >> 2, t = lane & 3;
    const int wm = w >> 1, wn = w & 1;
    const int m0 = blockIdx.x * 128;
    const int n0 = blockIdx.y * 128;
    const int mat = blockIdx.z;
    const __half2* __restrict__ Wp = &g_Wp[mat * (DIN / 2) * DHEAD];

    const int ar = tid >> 1;
    const int ak = (tid & 1) << 4;
    const int acb = (tid & 1) << 1;
    const int aq = (ar >> 1) & 3;
    const int bn = tid & 127;
    const int bcb = (tid >> 7) << 1;
    const int bq = (bn >> 1) & 3;

    float4 aR[4];
    unsigned bR[8];

    {
        const float* ap = &feat[(size_t)(m0 + ar) * DIN + ak];
        aR[0] = *(const float4*)(ap);
        aR[1] = *(const float4*)(ap + 4);
        aR[2] = *(const float4*)(ap + 8);
        aR[3] = *(const float4*)(ap + 12);
        const __half2* bp = &Wp[(size_t)(bcb * 4) * DHEAD + n0 + bn];
#pragma unroll
        for (int jj = 0; jj < 8; jj++) bR[jj] = *(const unsigned*)&bp[(size_t)jj * DHEAD];
    }

    float acc[2][8][4];
#pragma unroll
    for (int mt = 0; mt < 2; mt++)
#pragma unroll
        for (int nt = 0; nt < 8; nt++)
#pragma unroll
            for (int q = 0; q < 4; q++) acc[mt][nt][q] = 0.f;

    for (int it = 0; it < 16; it++) {
        {
            uint4 hq0, hq1, lq0, lq1;
            hq0.x = pack_hi(aR[0].x, aR[0].y); hq0.y = pack_hi(aR[0].z, aR[0].w);
            hq0.z = pack_hi(aR[1].x, aR[1].y); hq0.w = pack_hi(aR[1].z, aR[1].w);
            hq1.x = pack_hi(aR[2].x, aR[2].y); hq1.y = pack_hi(aR[2].z, aR[2].w);
            hq1.z = pack_hi(aR[3].x, aR[3].y); hq1.w = pack_hi(aR[3].z, aR[3].w);
            lq0.x = pack_lo(aR[0].x, aR[0].y); lq0.y = pack_lo(aR[0].z, aR[0].w);
            lq0.z = pack_lo(aR[1].x, aR[1].y); lq0.w = pack_lo(aR[1].z, aR[1].w);
            lq1.x = pack_lo(aR[2].x, aR[2].y); lq1.y = pack_lo(aR[2].z, aR[2].w);
            lq1.z = pack_lo(aR[3].x, aR[3].y); lq1.w = pack_lo(aR[3].z, aR[3].w);
            *(uint4*)&As[0][ar][((acb    ) ^ aq) << 2] = hq0;
            *(uint4*)&As[0][ar][((acb + 1) ^ aq) << 2] = hq1;
            *(uint4*)&As[1][ar][((acb    ) ^ aq) << 2] = lq0;
            *(uint4*)&As[1][ar][((acb + 1) ^ aq) << 2] = lq1;
            uint4 bq0, bq1;
            bq0.x = bR[0]; bq0.y = bR[1]; bq0.z = bR[2]; bq0.w = bR[3];
            bq1.x = bR[4]; bq1.y = bR[5]; bq1.z = bR[6]; bq1.w = bR[7];
            *(uint4*)&Bs[bn][((bcb    ) ^ bq) << 2] = bq0;
            *(uint4*)&Bs[bn][((bcb + 1) ^ bq) << 2] = bq1;
        }
        __syncthreads();

        if (it + 1 < 16) {
            const int kb = (it + 1) << 5;
            const float* ap = &feat[(size_t)(m0 + ar) * DIN + kb + ak];
            aR[0] = *(const float4*)(ap);
            aR[1] = *(const float4*)(ap + 4);
            aR[2] = *(const float4*)(ap + 8);
            aR[3] = *(const float4*)(ap + 12);
            const __half2* bp = &Wp[(size_t)(kb / 2 + bcb * 4) * DHEAD + n0 + bn];
#pragma unroll
            for (int jj = 0; jj < 8; jj++) bR[jj] = *(const unsigned*)&bp[(size_t)jj * DHEAD];
        }

#pragma unroll
        for (int ks = 0; ks < 2; ks++) {
            unsigned bfr[8][2];
#pragma unroll
            for (int nt = 0; nt < 8; nt++) {
                int n = 64 * wn + 8 * nt + g;
                int qn = (n >> 1) & 3;
                bfr[nt][0] = *(const unsigned*)&Bs[n][(((2 * ks    ) ^ qn) << 2) + t];
                bfr[nt][1] = *(const unsigned*)&Bs[n][(((2 * ks + 1) ^ qn) << 2) + t];
            }
#pragma unroll
            for (int sp = 0; sp < 2; sp++) {
#pragma unroll
                for (int mt = 0; mt < 2; mt++) {
                    int r = 32 * wm + 16 * mt + g;
                    int qr = (r >> 1) & 3;
                    unsigned a0 = *(const unsigned*)&As[sp][r    ][(((2 * ks    ) ^ qr) << 2) + t];
                    unsigned a1 = *(const unsigned*)&As[sp][r + 8][(((2 * ks    ) ^ qr) << 2) + t];
                    unsigned a2 = *(const unsigned*)&As[sp][r    ][(((2 * ks + 1) ^ qr) << 2) + t];
                    unsigned a3 = *(const unsigned*)&As[sp][r + 8][(((2 * ks + 1) ^ qr) << 2) + t];
#pragma unroll
                    for (int nt = 0; nt < 8; nt++)
                        mma_f16(acc[mt][nt][0], acc[mt][nt][1], acc[mt][nt][2], acc[mt][nt][3],
                                a0, a1, a2, a3, bfr[nt][0], bfr[nt][1]);
                }
            }
        }
        __syncthreads();
    }

    // Q scale folds 1/sqrt(256) AND log2(e) so the epilogue can use raw ex2.
    const float scale = (mat == 0) ? 0.09014020181552054f : 1.0f;
#pragma unroll
    for (int mt = 0; mt < 2; mt++) {
        int r = m0 + 32 * wm + 16 * mt + g;
#pragma unroll
        for (int nt = 0; nt < 8; nt++) {
            int col = n0 + 64 * wn + 8 * nt + 2 * t;
            __half h00 = __float2half_rn(acc[mt][nt][0] * scale);
            __half h01 = __float2half_rn(acc[mt][nt][1] * scale);
            __half h10 = __float2half_rn(acc[mt][nt][2] * scale);
            __half h11 = __float2half_rn(acc[mt][nt][3] * scale);
            if (mat == 2) {
                g_Vt[(size_t)col * NTOK + r] = h00;
                g_Vt[(size_t)(col + 1) * NTOK + r] = h01;
                g_Vt[(size_t)col * NTOK + r + 8] = h10;
                g_Vt[(size_t)(col + 1) * NTOK + r + 8] = h11;
            } else {
                __half* dst = (mat == 0) ? g_Qh : g_Kh;
                *(__half2*)&dst[(size_t)r * DHEAD + col] = __halves2half2(h00, h01);
                *(__half2*)&dst[(size_t)(r + 8) * DHEAD + col] = __halves2half2(h10, h11);
            }
        }
    }
}

// ---------------- kernel 2: fp16 attention, ungated epilogue, 3 full barriers ----------------
#define SMO_Q   0u        // [128][256] half, 16B-granule xor swizzle
#define SMO_K0  65536u
#define SMO_K1  98304u
#define SMO_V   131072u   // [256][64] half (V^T)
#define SMO_C   163840u   // 8 warp-private regions x 4KB: [32 rows][8 f4, f4^(row&7)]
#define SMO_P   196608u   // [128] rows x 144B
#define SMO_L   215040u
#define SMEM_DYN (215040u + 1024u)

__global__ __launch_bounds__(256, 1) void attn_kernel(const float* __restrict__ cnt) {
    extern __shared__ char sm[];
    const uint32_t sb = smem_u32(sm);

    const int tid = threadIdx.x, w = tid >> 5, lane = tid & 31;
    const int g = lane >> 2, t = lane & 3;
    const int wm = w & 3, wh = w >> 2;
    const int m0 = blockIdx.x * BM;
    const int sp = blockIdx.y;
    const int jb0 = sp * (NTOK / NSPLIT);

    const int lr = lane & 7;
    const int lm = (lane >> 3) & 1;
    const int lh = lane >> 4;

    const int ar0 = 32 * wm + lr + 8 * lm;
    const uint32_t qb0 = sb + SMO_Q + (uint32_t)ar0 * 512u;
    const uint32_t qb1 = qb0 + 16u * 512u;
    const uint32_t pb0 = sb + SMO_P + (uint32_t)ar0 * 144u;
    const uint32_t pb1 = pb0 + 16u * 144u;
    const int bnr = lr + 8 * lh;
    const uint32_t kroff = (uint32_t)(32 * wh + bnr) * 512u;
    const uint32_t vb = sb + SMO_V + (uint32_t)(128 * wh + bnr) * 128u;

    // warp-private C region: 4KB per warp; this thread's cp16 targets
    const uint32_t cw = sb + SMO_C + (uint32_t)w * 4096u;
    const float* crow = &cnt[(size_t)(m0 + 32 * wm) * NTOK + 32 * wh];  // + jb at use
    const int crr = lane >> 3;           // rows loaded: crr, crr+4, ... (8 chunks)
    const int cf4 = lane & 7;

#pragma unroll
    for (int i = 0; i < 16; i++) {
        int e = tid + 256 * i;
        int r = e >> 5, blk = e & 31;
        uint32_t d = sb + SMO_Q + (uint32_t)r * 512u + (uint32_t)((blk ^ (r & 7)) << 4);
        cp16(d, &g_Qh[(size_t)(m0 + r) * DHEAD + 8 * blk]);
    }
#pragma unroll
    for (int i = 0; i < 8; i++) {
        int e = tid + 256 * i;
        int r = e >> 5, blk = e & 31;
        uint32_t d = sb + SMO_K0 + (uint32_t)r * 512u + (uint32_t)((blk ^ (r & 7)) << 4);
        cp16(d, &g_Kh[(size_t)(jb0 + r) * DHEAD + 8 * blk]);
    }
    CP_COMMIT();

    float O[2][16][4];
#pragma unroll
    for (int mt = 0; mt < 2; mt++)
#pragma unroll
        for (int nt = 0; nt < 16; nt++)
#pragma unroll
            for (int q = 0; q < 4; q++) O[mt][nt][q] = 0.f;
    float lA[2] = {0.f, 0.f}, lB[2] = {0.f, 0.f};

    for (int j = 0; j < JBLOCKS; j++) {
        const int jb = jb0 + j * BN;
        __syncthreads();   // b1: prev AV done with V/P; prev epilogue done with C

        // ---- issue V_j (all threads) + warp-private C_j (one group) ----
#pragma unroll
        for (int i = 0; i < 8; i++) {
            int e = tid + 256 * i;
            int dd = e >> 3, blk = e & 7;
            uint32_t d = sb + SMO_V + (uint32_t)dd * 128u + (uint32_t)((blk ^ (dd & 7)) << 4);
            cp16(d, &g_Vt[(size_t)dd * NTOK + jb + 8 * blk]);
        }
#pragma unroll
        for (int i = 0; i < 8; i++) {
            int row = crr + 4 * i;       // 0..31 over 8 iters
            uint32_t d = cw + (uint32_t)row * 128u + (uint32_t)((cf4 ^ (row & 7)) << 4);
            cp16(d, crow + (size_t)row * NTOK + jb + 4 * cf4);
        }
        CP_COMMIT();

        // ---- issue K_{j+1} ----
        if (j + 1 < JBLOCKS) {
            uint32_t kb = ((j + 1) & 1) ? SMO_K1 : SMO_K0;
#pragma unroll
            for (int i = 0; i < 8; i++) {
                int e = tid + 256 * i;
                int r = e >> 5, blk = e & 31;
                uint32_t d = sb + kb + (uint32_t)r * 512u + (uint32_t)((blk ^ (r & 7)) << 4);
                cp16(d, &g_Kh[(size_t)(jb + BN + r) * DHEAD + 8 * blk]);
            }
        }
        CP_COMMIT();

        CP_WAIT(2);
        __syncthreads();   // b2: K_j visible

        // ---- QK_j ----
        const uint32_t kbuf = sb + ((j & 1) ? SMO_K1 : SMO_K0) + kroff;
        float S[2][4][4];
#pragma unroll
        for (int mt = 0; mt < 2; mt++)
#pragma unroll
            for (int nt = 0; nt < 4; nt++)
#pragma unroll
                for (int q = 0; q < 4; q++) S[mt][nt][q] = 0.f;

#pragma unroll
        for (int s = 0; s < 16; s++) {
            const uint32_t xa = (uint32_t)(((2 * s + lh) ^ lr) << 4);
            const uint32_t xb = (uint32_t)(((2 * s + lm) ^ lr) << 4);
            unsigned a0[4], a1[4], b0[4], b1[4];
            ldsm4(a0[0], a0[1], a0[2], a0[3], qb0 + xa);
            ldsm4(a1[0], a1[1], a1[2], a1[3], qb1 + xa);
            ldsm4(b0[0], b0[1], b0[2], b0[3], kbuf + xb);
            ldsm4(b1[0], b1[1], b1[2], b1[3], kbuf + 16u * 512u + xb);
            mma_f16(S[0][0][0], S[0][0][1], S[0][0][2], S[0][0][3], a0[0], a0[1], a0[2], a0[3], b0[0], b0[1]);
            mma_f16(S[0][1][0], S[0][1][1], S[0][1][2], S[0][1][3], a0[0], a0[1], a0[2], a0[3], b0[2], b0[3]);
            mma_f16(S[0][2][0], S[0][2][1], S[0][2][2], S[0][2][3], a0[0], a0[1], a0[2], a0[3], b1[0], b1[1]);
            mma_f16(S[0][3][0], S[0][3][1], S[0][3][2], S[0][3][3], a0[0], a0[1], a0[2], a0[3], b1[2], b1[3]);
            mma_f16(S[1][0][0], S[1][0][1], S[1][0][2], S[1][0][3], a1[0], a1[1], a1[2], a1[3], b0[0], b0[1]);
            mma_f16(S[1][1][0], S[1][1][1], S[1][1][2], S[1][1][3], a1[0], a1[1], a1[2], a1[3], b0[2], b0[3]);
            mma_f16(S[1][2][0], S[1][2][1], S[1][2][2], S[1][2][3], a1[0], a1[1], a1[2], a1[3], b1[0], b1[1]);
            mma_f16(S[1][3][0], S[1][3][1], S[1][3][2], S[1][3][3], a1[0], a1[1], a1[2], a1[3], b1[2], b1[3]);
        }

        // ---- epilogue, ungated: own warp's C suffices ----
        CP_WAIT(1);
        __syncwarp();
        const char* Cw = sm + SMO_C + w * 4096;
        char* Ps = sm + SMO_P;
#pragma unroll
        for (int mt = 0; mt < 2; mt++) {
            int lrA = g + 16 * mt, lrB = lrA + 8;       // (row&7) == g for all four
            int rA = 32 * wm + lrA, rB = 32 * wm + lrB; // global-in-tile rows for P
            float sA = 0.f, sB = 0.f;
#pragma unroll
            for (int nt = 0; nt < 4; nt++) {
                int co = (((2 * nt + (t >> 1)) ^ g) << 4) + ((t & 1) << 3);
                float2 cA = *(const float2*)(Cw + lrA * 128 + co);
                float2 cB = *(const float2*)(Cw + lrB * 128 + co);
                float p0 = ex2f(S[mt][nt][0]) * cA.x;
                float p1 = ex2f(S[mt][nt][1]) * cA.y;
                float p2 = ex2f(S[mt][nt][2]) * cB.x;
                float p3 = ex2f(S[mt][nt][3]) * cB.y;
                sA += p0 + p1;
                sB += p2 + p3;
                int q = (16 * wh + 4 * nt + t) << 2;
                *(__half2*)(Ps + rA * 144 + q) = __halves2half2(__float2half_rn(p0), __float2half_rn(p1));
                *(__half2*)(Ps + rB * 144 + q) = __halves2half2(__float2half_rn(p2), __float2half_rn(p3));
            }
            sA += __shfl_xor_sync(0xffffffffu, sA, 1);
            sA += __shfl_xor_sync(0xffffffffu, sA, 2);
            sB += __shfl_xor_sync(0xffffffffu, sB, 1);
            sB += __shfl_xor_sync(0xffffffffu, sB, 2);
            lA[mt] += sA;
            lB[mt] += sB;
        }
        __syncthreads();   // b3: V (all threads' groups drained) + P visible for AV

        // ---- AV_j ----
#pragma unroll
        for (int s = 0; s < 4; s++) {
            const uint32_t xp = (uint32_t)((2 * s + lh) << 4);
            const uint32_t xv = (uint32_t)(((2 * s + lm) ^ lr) << 4);
            unsigned pa0[4], pa1[4];
            ldsm4(pa0[0], pa0[1], pa0[2], pa0[3], pb0 + xp);
            ldsm4(pa1[0], pa1[1], pa1[2], pa1[3], pb1 + xp);
#pragma unroll
            for (int p = 0; p < 8; p++) {
                unsigned vv[4];
                ldsm4(vv[0], vv[1], vv[2], vv[3], vb + (uint32_t)p * 2048u + xv);
                mma_f16(O[0][2 * p][0], O[0][2 * p][1], O[0][2 * p][2], O[0][2 * p][3],
                        pa0[0], pa0[1], pa0[2], pa0[3], vv[0], vv[1]);
                mma_f16(O[0][2 * p + 1][0], O[0][2 * p + 1][1], O[0][2 * p + 1][2], O[0][2 * p + 1][3],
                        pa0[0], pa0[1], pa0[2], pa0[3], vv[2], vv[3]);
                mma_f16(O[1][2 * p][0], O[1][2 * p][1], O[1][2 * p][2], O[1][2 * p][3],
                        pa1[0], pa1[1], pa1[2], pa1[3], vv[0], vv[1]);
                mma_f16(O[1][2 * p + 1][0], O[1][2 * p + 1][1], O[1][2 * p + 1][2], O[1][2 * p + 1][3],
                        pa1[0], pa1[1], pa1[2], pa1[3], vv[2], vv[3]);
            }
        }
    }

    // ---- O writeout ----
    const int rA0 = 32 * wm + g, rB0 = rA0 + 8;
#pragma unroll
    for (int mt = 0; mt < 2; mt++) {
        int rA = m0 + rA0 + 16 * mt, rB = m0 + rB0 + 16 * mt;
#pragma unroll
        for (int nt = 0; nt < 16; nt++) {
            int col = 128 * wh + 8 * nt + 2 * t;
            *(float2*)&g_Op[sp][rA][col] = make_float2(O[mt][nt][0], O[mt][nt][1]);
            *(float2*)&g_Op[sp][rB][col] = make_float2(O[mt][nt][2], O[mt][nt][3]);
        }
    }

    float* Lr = (float*)(sm + SMO_L);
    if (t == 0) {
#pragma unroll
        for (int mt = 0; mt < 2; mt++) {
            Lr[wh * 128 + rA0 + 16 * mt] = lA[mt];
            Lr[wh * 128 + rB0 + 16 * mt] = lB[mt];
        }
    }
    __syncthreads();
    if (tid < 128) g_ls[sp][m0 + tid] = Lr[tid] + Lr[128 + tid];
}

// ---------------- kernel 3: combine + ELU (float4) ----------------
__global__ __launch_bounds__(256) void combine_kernel(float* __restrict__ out) {
    const int idx = blockIdx.x * 256 + threadIdx.x;     // 524288 threads
    const int row = idx >> 6;
    const int d4 = (idx & 63) << 2;
    float4 a = *(const float4*)&g_Op[0][row][d4];
    float4 b = *(const float4*)&g_Op[1][row][d4];
    float inv = 1.0f / (g_ls[0][row] + g_ls[1][row]);
    float r0 = (a.x + b.x) * inv, r1 = (a.y + b.y) * inv;
    float r2 = (a.z + b.z) * inv, r3 = (a.w + b.w) * inv;
    float4 o;
    o.x = (r0 > 0.f) ? r0 : expm1f(r0);
    o.y = (r1 > 0.f) ? r1 : expm1f(r1);
    o.z = (r2 > 0.f) ? r2 : expm1f(r2);
    o.w = (r3 > 0.f) ? r3 : expm1f(r3);
    *(float4*)&out[(size_t)row * DHEAD + d4] = o;
}

// ---------------- launch ----------------
extern "C" void kernel_launch(void* const* d_in, const int* in_sizes, int n_in,
                              void* d_out, int out_size) {
    (void)in_sizes; (void)n_in; (void)out_size;
    const float* feat = (const float*)d_in[0];
    const float* cnt = (const float*)d_in[1];
    const float* Wq = (const float*)d_in[2];
    const float* Wk = (const float*)d_in[3];
    const float* Wv = (const float*)d_in[4];

    prep_w<<<(3 * (DIN / 2) * DHEAD + 255) / 256, 256>>>(Wq, Wk, Wv);

    proj_kernel<<<dim3(NTOK / 128, DHEAD / 128, 3), 256>>>(feat);

    cudaFuncSetAttribute(attn_kernel, cudaFuncAttributeMaxDynamicSharedMemorySize, (int)SMEM_DYN);
    attn_kernel<<<dim3(NTOK / BM, NSPLIT), 256, SMEM_DYN>>>(cnt);

    combine_kernel<<<NTOK * DHEAD / 1024, 256>>>((float*)d_out);
}

// round 12
// speedup vs baseline: 1.2776x; 1.0302x over previous
#include <cuda_runtime.h>
#include <cuda_fp16.h>
#include <cstdint>

#define NTOK 8192
#define DIN  512
#define DHEAD 256
#define NSPLIT 2
#define BM 128
#define BN 64
#define JBLOCKS (NTOK / NSPLIT / BN)   // 64

// ---------------- scratch ----------------
__device__ __half2 g_Wp[3 * (DIN / 2) * DHEAD];  // W packed as k-pairs, fp16
__device__ __half  g_Qh[NTOK * DHEAD];        // fp16, pre-scaled by log2e/16
__device__ __half  g_Kh[NTOK * DHEAD];        // fp16
__device__ __half  g_Vt[DHEAD * NTOK];        // V transposed [d][tok], fp16
__device__ float   g_Op[NSPLIT][NTOK][DHEAD];
__device__ float   g_ls[NSPLIT][NTOK];

// ---------------- helpers ----------------
__device__ __forceinline__ uint32_t smem_u32(const void* p) {
    uint32_t a;
    asm("{ .reg .u64 t; cvta.to.shared.u64 t, %1; cvt.u32.u64 %0, t; }" : "=r"(a) : "l"(p));
    return a;
}
__device__ __forceinline__ void cp16(uint32_t dst, const void* src) {
    asm volatile("cp.async.cg.shared.global [%0], [%1], 16;" :: "r"(dst), "l"(src));
}
#define CP_COMMIT() asm volatile("cp.async.commit_group;" ::: "memory")
#define CP_WAIT(n)  asm volatile("cp.async.wait_group %0;" :: "n"(n) : "memory")

__device__ __forceinline__ void ldsm4(unsigned& r0, unsigned& r1, unsigned& r2, unsigned& r3,
                                      uint32_t a) {
    asm volatile("ldmatrix.sync.aligned.m8n8.x4.shared.b16 {%0,%1,%2,%3}, [%4];"
                 : "=r"(r0), "=r"(r1), "=r"(r2), "=r"(r3) : "r"(a));
}

__device__ __forceinline__ void mma_f16(float& c0, float& c1, float& c2, float& c3,
                                        unsigned a0, unsigned a1, unsigned a2, unsigned a3,
                                        unsigned b0, unsigned b1) {
    asm volatile(
        "mma.sync.aligned.m16n8k16.row.col.f32.f16.f16.f32 "
        "{%0,%1,%2,%3}, {%4,%5,%6,%7}, {%8,%9}, {%0,%1,%2,%3};"
        : "+f"(c0), "+f"(c1), "+f"(c2), "+f"(c3)
        : "r"(a0), "r"(a1), "r"(a2), "r"(a3), "r"(b0), "r"(b1));
}

__device__ __forceinline__ float ex2f(float x) {
    float r; asm("ex2.approx.f32 %0, %1;" : "=f"(r) : "f"(x)); return r;
}

__device__ __forceinline__ unsigned pack_hi(float a, float b) {
    __half2 h = __halves2half2(__float2half_rn(a), __float2half_rn(b));
    return *(unsigned*)&h;
}
__device__ __forceinline__ unsigned pack_lo(float a, float b) {
    float ra = a - __half2float(__float2half_rn(a));
    float rb = b - __half2float(__float2half_rn(b));
    __half2 h = __halves2half2(__float2half_rn(ra), __float2half_rn(rb));
    return *(unsigned*)&h;
}

// ---------------- kernel 0: pack W (1.5 MB one-time) ----------------
__global__ __launch_bounds__(256) void prep_w(const float* __restrict__ Wq,
                                              const float* __restrict__ Wk,
                                              const float* __restrict__ Wv) {
    const int j = blockIdx.x * 256 + threadIdx.x;
    const int WSZ = (DIN / 2) * DHEAD;
    if (j < 3 * WSZ) {
        int mat = j / WSZ;
        int r = j - mat * WSZ;
        int k2 = r / DHEAD, n = r % DHEAD;
        const float* __restrict__ W = (mat == 0) ? Wq : ((mat == 1) ? Wk : Wv);
        g_Wp[j] = __halves2half2(__float2half_rn(W[(size_t)(2 * k2) * DHEAD + n]),
                                 __float2half_rn(W[(size_t)(2 * k2 + 1) * DHEAD + n]));
    }
}

// ---------------- kernel 1: QKV projection v3 — BM=64, BN=128, 32x32 warp tiles ----------------
// 768 CTAs, ~80 regs -> 3 CTAs/SM for latency overlap. Same accumulation order as before.
__global__ __launch_bounds__(256) void proj_kernel(const float* __restrict__ feat) {
    __shared__ __align__(16) __half2 As[2][64][16];   // [hi/lo][row][chunk^((row>>1)&3) layout]
    __shared__ __align__(16) __half2 Bs[128][16];     // [col][chunk^((col>>1)&3)]

    const int tid = threadIdx.x;
    const int w = tid >> 5, lane = tid & 31, g = lane >> 2, t = lane & 3;
    const int wm = w >> 2;        // 0..1 : 32-row band
    const int wn = w & 3;         // 0..3 : 32-col band
    const int m0 = blockIdx.x * 64;
    const int n0 = blockIdx.y * 128;
    const int mat = blockIdx.z;
    const __half2* __restrict__ Wp = &g_Wp[mat * (DIN / 2) * DHEAD];

    // A: thread -> row tid>>2 (0..63), chunk tid&3 (8 halfs)
    const int ar = tid >> 2;
    const int ac = tid & 3;
    const int aq = (ar >> 1) & 3;
    // B: same as before (tile is 32k x 128 cols)
    const int bn = tid & 127;
    const int bcb = (tid >> 7) << 1;
    const int bq = (bn >> 1) & 3;

    float4 aR[2];
    unsigned bR[8];
    {
        const float* ap = &feat[(size_t)(m0 + ar) * DIN + ac * 8];
        aR[0] = *(const float4*)(ap);
        aR[1] = *(const float4*)(ap + 4);
        const __half2* bp = &Wp[(size_t)(bcb * 4) * DHEAD + n0 + bn];
#pragma unroll
        for (int jj = 0; jj < 8; jj++) bR[jj] = *(const unsigned*)&bp[(size_t)jj * DHEAD];
    }

    float acc[2][4][4];
#pragma unroll
    for (int mt = 0; mt < 2; mt++)
#pragma unroll
        for (int nt = 0; nt < 4; nt++)
#pragma unroll
            for (int q = 0; q < 4; q++) acc[mt][nt][q] = 0.f;

    for (int it = 0; it < 16; it++) {
        {
            uint4 hq, lq;
            hq.x = pack_hi(aR[0].x, aR[0].y); hq.y = pack_hi(aR[0].z, aR[0].w);
            hq.z = pack_hi(aR[1].x, aR[1].y); hq.w = pack_hi(aR[1].z, aR[1].w);
            lq.x = pack_lo(aR[0].x, aR[0].y); lq.y = pack_lo(aR[0].z, aR[0].w);
            lq.z = pack_lo(aR[1].x, aR[1].y); lq.w = pack_lo(aR[1].z, aR[1].w);
            *(uint4*)&As[0][ar][(ac ^ aq) << 2] = hq;
            *(uint4*)&As[1][ar][(ac ^ aq) << 2] = lq;
            uint4 bq0, bq1;
            bq0.x = bR[0]; bq0.y = bR[1]; bq0.z = bR[2]; bq0.w = bR[3];
            bq1.x = bR[4]; bq1.y = bR[5]; bq1.z = bR[6]; bq1.w = bR[7];
            *(uint4*)&Bs[bn][((bcb    ) ^ bq) << 2] = bq0;
            *(uint4*)&Bs[bn][((bcb + 1) ^ bq) << 2] = bq1;
        }
        __syncthreads();

        if (it + 1 < 16) {
            const int kb = (it + 1) << 5;
            const float* ap = &feat[(size_t)(m0 + ar) * DIN + kb + ac * 8];
            aR[0] = *(const float4*)(ap);
            aR[1] = *(const float4*)(ap + 4);
            const __half2* bp = &Wp[(size_t)(kb / 2 + bcb * 4) * DHEAD + n0 + bn];
#pragma unroll
            for (int jj = 0; jj < 8; jj++) bR[jj] = *(const unsigned*)&bp[(size_t)jj * DHEAD];
        }

#pragma unroll
        for (int ks = 0; ks < 2; ks++) {
            unsigned bfr[4][2];
#pragma unroll
            for (int nt = 0; nt < 4; nt++) {
                int n = 32 * wn + 8 * nt + g;
                int qn = (n >> 1) & 3;
                bfr[nt][0] = *(const unsigned*)&Bs[n][(((2 * ks    ) ^ qn) << 2) + t];
                bfr[nt][1] = *(const unsigned*)&Bs[n][(((2 * ks + 1) ^ qn) << 2) + t];
            }
#pragma unroll
            for (int sp = 0; sp < 2; sp++) {
#pragma unroll
                for (int mt = 0; mt < 2; mt++) {
                    int r = 32 * wm + 16 * mt + g;
                    int qr = (r >> 1) & 3;
                    unsigned a0 = *(const unsigned*)&As[sp][r    ][(((2 * ks    ) ^ qr) << 2) + t];
                    unsigned a1 = *(const unsigned*)&As[sp][r + 8][(((2 * ks    ) ^ qr) << 2) + t];
                    unsigned a2 = *(const unsigned*)&As[sp][r    ][(((2 * ks + 1) ^ qr) << 2) + t];
                    unsigned a3 = *(const unsigned*)&As[sp][r + 8][(((2 * ks + 1) ^ qr) << 2) + t];
#pragma unroll
                    for (int nt = 0; nt < 4; nt++)
                        mma_f16(acc[mt][nt][0], acc[mt][nt][1], acc[mt][nt][2], acc[mt][nt][3],
                                a0, a1, a2, a3, bfr[nt][0], bfr[nt][1]);
                }
            }
        }
        __syncthreads();
    }

    // Q scale folds 1/sqrt(256) AND log2(e).
    const float scale = (mat == 0) ? 0.09014020181552054f : 1.0f;
#pragma unroll
    for (int mt = 0; mt < 2; mt++) {
        int r = m0 + 32 * wm + 16 * mt + g;
#pragma unroll
        for (int nt = 0; nt < 4; nt++) {
            int col = n0 + 32 * wn + 8 * nt + 2 * t;
            __half h00 = __float2half_rn(acc[mt][nt][0] * scale);
            __half h01 = __float2half_rn(acc[mt][nt][1] * scale);
            __half h10 = __float2half_rn(acc[mt][nt][2] * scale);
            __half h11 = __float2half_rn(acc[mt][nt][3] * scale);
            if (mat == 2) {
                g_Vt[(size_t)col * NTOK + r] = h00;
                g_Vt[(size_t)(col + 1) * NTOK + r] = h01;
                g_Vt[(size_t)col * NTOK + r + 8] = h10;
                g_Vt[(size_t)(col + 1) * NTOK + r + 8] = h11;
            } else {
                __half* dst = (mat == 0) ? g_Qh : g_Kh;
                *(__half2*)&dst[(size_t)r * DHEAD + col] = __halves2half2(h00, h01);
                *(__half2*)&dst[(size_t)(r + 8) * DHEAD + col] = __halves2half2(h10, h11);
            }
        }
    }
}

// ---------------- kernel 2: fp16 attention, 2 full barriers/iter ----------------
#define SMO_Q   0u        // [128][256] half, 16B-granule xor swizzle
#define SMO_K0  65536u
#define SMO_K1  98304u
#define SMO_V   131072u   // [256][64] half (V^T)
#define SMO_C   163840u   // 8 warp-private regions x 4KB
#define SMO_P   196608u   // [128] rows x 144B
#define SMO_L   215040u
#define SMEM_DYN (215040u + 1024u)

__global__ __launch_bounds__(256, 1) void attn_kernel(const float* __restrict__ cnt) {
    extern __shared__ char sm[];
    const uint32_t sb = smem_u32(sm);

    const int tid = threadIdx.x, w = tid >> 5, lane = tid & 31;
    const int g = lane >> 2, t = lane & 3;
    const int wm = w & 3, wh = w >> 2;
    const int m0 = blockIdx.x * BM;
    const int sp = blockIdx.y;
    const int jb0 = sp * (NTOK / NSPLIT);

    const int lr = lane & 7;
    const int lm = (lane >> 3) & 1;
    const int lh = lane >> 4;

    const int ar0 = 32 * wm + lr + 8 * lm;
    const uint32_t qb0 = sb + SMO_Q + (uint32_t)ar0 * 512u;
    const uint32_t qb1 = qb0 + 16u * 512u;
    const uint32_t pb0 = sb + SMO_P + (uint32_t)ar0 * 144u;
    const uint32_t pb1 = pb0 + 16u * 144u;
    const int bnr = lr + 8 * lh;
    const uint32_t kroff = (uint32_t)(32 * wh + bnr) * 512u;
    const uint32_t vb = sb + SMO_V + (uint32_t)(128 * wh + bnr) * 128u;

    const uint32_t cw = sb + SMO_C + (uint32_t)w * 4096u;
    const float* crow = &cnt[(size_t)(m0 + 32 * wm) * NTOK + 32 * wh];
    const int crr = lane >> 3;
    const int cf4 = lane & 7;

    // prologue: Q + K_0 as the initial "K group"
#pragma unroll
    for (int i = 0; i < 16; i++) {
        int e = tid + 256 * i;
        int r = e >> 5, blk = e & 31;
        uint32_t d = sb + SMO_Q + (uint32_t)r * 512u + (uint32_t)((blk ^ (r & 7)) << 4);
        cp16(d, &g_Qh[(size_t)(m0 + r) * DHEAD + 8 * blk]);
    }
#pragma unroll
    for (int i = 0; i < 8; i++) {
        int e = tid + 256 * i;
        int r = e >> 5, blk = e & 31;
        uint32_t d = sb + SMO_K0 + (uint32_t)r * 512u + (uint32_t)((blk ^ (r & 7)) << 4);
        cp16(d, &g_Kh[(size_t)(jb0 + r) * DHEAD + 8 * blk]);
    }
    CP_COMMIT();

    float O[2][16][4];
#pragma unroll
    for (int mt = 0; mt < 2; mt++)
#pragma unroll
        for (int nt = 0; nt < 16; nt++)
#pragma unroll
            for (int q = 0; q < 4; q++) O[mt][nt][q] = 0.f;
    float lA[2] = {0.f, 0.f}, lB[2] = {0.f, 0.f};

    for (int j = 0; j < JBLOCKS; j++) {
        const int jb = jb0 + j * BN;

        // Only K_j's group can be outstanding here: complete it, then one barrier
        // publishes K_j AND confirms all warps done with V/P/C buffers (AV_{j-1} and
        // epilogue_{j-1} precede this point in every warp's program order).
        CP_WAIT(0);
        __syncthreads();   // b1

        // ---- issue V_j + warp-private C_j (group G_V) ----
#pragma unroll
        for (int i = 0; i < 8; i++) {
            int e = tid + 256 * i;
            int dd = e >> 3, blk = e & 7;
            uint32_t d = sb + SMO_V + (uint32_t)dd * 128u + (uint32_t)((blk ^ (dd & 7)) << 4);
            cp16(d, &g_Vt[(size_t)dd * NTOK + jb + 8 * blk]);
        }
#pragma unroll
        for (int i = 0; i < 8; i++) {
            int row = crr + 4 * i;
            uint32_t d = cw + (uint32_t)row * 128u + (uint32_t)((cf4 ^ (row & 7)) << 4);
            cp16(d, crow + (size_t)row * NTOK + jb + 4 * cf4);
        }
        CP_COMMIT();

        // ---- issue K_{j+1} (group G_K; waited at next iter's top) ----
        if (j + 1 < JBLOCKS) {
            uint32_t kb = ((j + 1) & 1) ? SMO_K1 : SMO_K0;
#pragma unroll
            for (int i = 0; i < 8; i++) {
                int e = tid + 256 * i;
                int r = e >> 5, blk = e & 31;
                uint32_t d = sb + kb + (uint32_t)r * 512u + (uint32_t)((blk ^ (r & 7)) << 4);
                cp16(d, &g_Kh[(size_t)(jb + BN + r) * DHEAD + 8 * blk]);
            }
        }
        CP_COMMIT();

        // ---- QK_j ----
        const uint32_t kbuf = sb + ((j & 1) ? SMO_K1 : SMO_K0) + kroff;
        float S[2][4][4];
#pragma unroll
        for (int mt = 0; mt < 2; mt++)
#pragma unroll
            for (int nt = 0; nt < 4; nt++)
#pragma unroll
                for (int q = 0; q < 4; q++) S[mt][nt][q] = 0.f;

#pragma unroll
        for (int s = 0; s < 16; s++) {
            const uint32_t xa = (uint32_t)(((2 * s + lh) ^ lr) << 4);
            const uint32_t xb = (uint32_t)(((2 * s + lm) ^ lr) << 4);
            unsigned a0[4], a1[4], b0[4], b1[4];
            ldsm4(a0[0], a0[1], a0[2], a0[3], qb0 + xa);
            ldsm4(a1[0], a1[1], a1[2], a1[3], qb1 + xa);
            ldsm4(b0[0], b0[1], b0[2], b0[3], kbuf + xb);
            ldsm4(b1[0], b1[1], b1[2], b1[3], kbuf + 16u * 512u + xb);
            mma_f16(S[0][0][0], S[0][0][1], S[0][0][2], S[0][0][3], a0[0], a0[1], a0[2], a0[3], b0[0], b0[1]);
            mma_f16(S[0][1][0], S[0][1][1], S[0][1][2], S[0][1][3], a0[0], a0[1], a0[2], a0[3], b0[2], b0[3]);
            mma_f16(S[0][2][0], S[0][2][1], S[0][2][2], S[0][2][3], a0[0], a0[1], a0[2], a0[3], b1[0], b1[1]);
            mma_f16(S[0][3][0], S[0][3][1], S[0][3][2], S[0][3][3], a0[0], a0[1], a0[2], a0[3], b1[2], b1[3]);
            mma_f16(S[1][0][0], S[1][0][1], S[1][0][2], S[1][0][3], a1[0], a1[1], a1[2], a1[3], b0[0], b0[1]);
            mma_f16(S[1][1][0], S[1][1][1], S[1][1][2], S[1][1][3], a1[0], a1[1], a1[2], a1[3], b0[2], b0[3]);
            mma_f16(S[1][2][0], S[1][2][1], S[1][2][2], S[1][2][3], a1[0], a1[1], a1[2], a1[3], b1[0], b1[1]);
            mma_f16(S[1][3][0], S[1][3][1], S[1][3][2], S[1][3][3], a1[0], a1[1], a1[2], a1[3], b1[2], b1[3]);
        }

        // ---- epilogue, ungated: G_V complete => own warp's C readable ----
        CP_WAIT(1);
        __syncwarp();
        const char* Cw = sm + SMO_C + w * 4096;
        char* Ps = sm + SMO_P;
#pragma unroll
        for (int mt = 0; mt < 2; mt++) {
            int lrA = g + 16 * mt, lrB = lrA + 8;
            int rA = 32 * wm + lrA, rB = 32 * wm + lrB;
            float sA = 0.f, sB = 0.f;
#pragma unroll
            for (int nt = 0; nt < 4; nt++) {
                int co = (((2 * nt + (t >> 1)) ^ g) << 4) + ((t & 1) << 3);
                float2 cA = *(const float2*)(Cw + lrA * 128 + co);
                float2 cB = *(const float2*)(Cw + lrB * 128 + co);
                float p0 = ex2f(S[mt][nt][0]) * cA.x;
                float p1 = ex2f(S[mt][nt][1]) * cA.y;
                float p2 = ex2f(S[mt][nt][2]) * cB.x;
                float p3 = ex2f(S[mt][nt][3]) * cB.y;
                sA += p0 + p1;
                sB += p2 + p3;
                int q = (16 * wh + 4 * nt + t) << 2;
                *(__half2*)(Ps + rA * 144 + q) = __halves2half2(__float2half_rn(p0), __float2half_rn(p1));
                *(__half2*)(Ps + rB * 144 + q) = __halves2half2(__float2half_rn(p2), __float2half_rn(p3));
            }
            sA += __shfl_xor_sync(0xffffffffu, sA, 1);
            sA += __shfl_xor_sync(0xffffffffu, sA, 2);
            sB += __shfl_xor_sync(0xffffffffu, sB, 1);
            sB += __shfl_xor_sync(0xffffffffu, sB, 2);
            lA[mt] += sA;
            lB[mt] += sB;
        }
        __syncthreads();   // b2: P + V visible to all warps (every thread CP_WAIT(1)'d G_V)

        // ---- AV_j ----
#pragma unroll
        for (int s = 0; s < 4; s++) {
            const uint32_t xp = (uint32_t)((2 * s + lh) << 4);
            const uint32_t xv = (uint32_t)(((2 * s + lm) ^ lr) << 4);
            unsigned pa0[4], pa1[4];
            ldsm4(pa0[0], pa0[1], pa0[2], pa0[3], pb0 + xp);
            ldsm4(pa1[0], pa1[1], pa1[2], pa1[3], pb1 + xp);
#pragma unroll
            for (int p = 0; p < 8; p++) {
                unsigned vv[4];
                ldsm4(vv[0], vv[1], vv[2], vv[3], vb + (uint32_t)p * 2048u + xv);
                mma_f16(O[0][2 * p][0], O[0][2 * p][1], O[0][2 * p][2], O[0][2 * p][3],
                        pa0[0], pa0[1], pa0[2], pa0[3], vv[0], vv[1]);
                mma_f16(O[0][2 * p + 1][0], O[0][2 * p + 1][1], O[0][2 * p + 1][2], O[0][2 * p + 1][3],
                        pa0[0], pa0[1], pa0[2], pa0[3], vv[2], vv[3]);
                mma_f16(O[1][2 * p][0], O[1][2 * p][1], O[1][2 * p][2], O[1][2 * p][3],
                        pa1[0], pa1[1], pa1[2], pa1[3], vv[0], vv[1]);
                mma_f16(O[1][2 * p + 1][0], O[1][2 * p + 1][1], O[1][2 * p + 1][2], O[1][2 * p + 1][3],
                        pa1[0], pa1[1], pa1[2], pa1[3], vv[2], vv[3]);
            }
        }
    }

    // ---- O writeout ----
    const int rA0 = 32 * wm + g, rB0 = rA0 + 8;
#pragma unroll
    for (int mt = 0; mt < 2; mt++) {
        int rA = m0 + rA0 + 16 * mt, rB = m0 + rB0 + 16 * mt;
#pragma unroll
        for (int nt = 0; nt < 16; nt++) {
            int col = 128 * wh + 8 * nt + 2 * t;
            *(float2*)&g_Op[sp][rA][col] = make_float2(O[mt][nt][0], O[mt][nt][1]);
            *(float2*)&g_Op[sp][rB][col] = make_float2(O[mt][nt][2], O[mt][nt][3]);
        }
    }

    float* Lr = (float*)(sm + SMO_L);
    if (t == 0) {
#pragma unroll
        for (int mt = 0; mt < 2; mt++) {
            Lr[wh * 128 + rA0 + 16 * mt] = lA[mt];
            Lr[wh * 128 + rB0 + 16 * mt] = lB[mt];
        }
    }
    __syncthreads();
    if (tid < 128) g_ls[sp][m0 + tid] = Lr[tid] + Lr[128 + tid];
}

// ---------------- kernel 3: combine + ELU (2x float4 per thread) ----------------
__global__ __launch_bounds__(256) void combine_kernel(float* __restrict__ out) {
    const int base = (blockIdx.x * 256 + threadIdx.x) * 2;   // float4 index
#pragma unroll
    for (int u = 0; u < 2; u++) {
        int idx = base + u;
        int row = idx >> 6;
        int d4 = (idx & 63) << 2;
        float4 a = *(const float4*)&g_Op[0][row][d4];
        float4 b = *(const float4*)&g_Op[1][row][d4];
        float inv = 1.0f / (g_ls[0][row] + g_ls[1][row]);
        float r0 = (a.x + b.x) * inv, r1 = (a.y + b.y) * inv;
        float r2 = (a.z + b.z) * inv, r3 = (a.w + b.w) * inv;
        float4 o;
        o.x = (r0 > 0.f) ? r0 : expm1f(r0);
        o.y = (r1 > 0.f) ? r1 : expm1f(r1);
        o.z = (r2 > 0.f) ? r2 : expm1f(r2);
        o.w = (r3 > 0.f) ? r3 : expm1f(r3);
        *(float4*)&out[(size_t)row * DHEAD + d4] = o;
    }
}

// ---------------- launch ----------------
extern "C" void kernel_launch(void* const* d_in, const int* in_sizes, int n_in,
                              void* d_out, int out_size) {
    (void)in_sizes; (void)n_in; (void)out_size;
    const float* feat = (const float*)d_in[0];
    const float* cnt = (const float*)d_in[1];
    const float* Wq = (const float*)d_in[2];
    const float* Wk = (const float*)d_in[3];
    const float* Wv = (const float*)d_in[4];

    prep_w<<<(3 * (DIN / 2) * DHEAD + 255) / 256, 256>>>(Wq, Wk, Wv);

    proj_kernel<<<dim3(NTOK / 64, DHEAD / 128, 3), 256>>>(feat);

    cudaFuncSetAttribute(attn_kernel, cudaFuncAttributeMaxDynamicSharedMemorySize, (int)SMEM_DYN);
    attn_kernel<<<dim3(NTOK / BM, NSPLIT), 256, SMEM_DYN>>>(cnt);

    combine_kernel<<<NTOK * DHEAD / 2048, 256>>>((float*)d_out);
}